// round 1
// baseline (speedup 1.0000x reference)
#include <cuda_runtime.h>
#include <math.h>

#define EPSV 1e-5f

// Problem dims
#define NB   4
#define CINC 128
#define CO   256
#define HH   64
#define WW   64
#define LATD 256
#define NG   16
#define NS   64          // axial sequence length
#define NP_FULL 4096     // 64*64
#define NP_HALF 1024     // 32*32

// ---------------- scratch (device globals; no allocation) ----------------
__device__ float g_y[NB * CO * HH * WW];          // 4.19M floats (16 MB)
__device__ float g_qkv[NB * 2 * CO * HH * WW];    // 8.39M floats (32 MB)
__device__ float g_py[NB * CO * 32 * 32];         // 1.05M
__device__ float g_px[NB * CINC * 32 * 32];       // 0.52M
__device__ float g_sb[4096];                      // [0:2048) lin_in scale/bias, [2048:4096) lin_out

// ---------------- latent -> per-(b,ch) scale/bias -----------------------
__global__ void sb_kernel(const float* __restrict__ latent,
                          const float* __restrict__ lin_in,
                          const float* __restrict__ lin_out,
                          float* __restrict__ sb)
{
    int idx = blockIdx.x * blockDim.x + threadIdx.x;   // 0..4095
    if (idx >= 4096) return;
    int which = idx >> 11;          // 0: lin_in, 1: lin_out
    int b = (idx >> 9) & 3;
    int j = idx & 511;
    const float* lin = which ? lin_out : lin_in;
    const float* lt = latent + b * LATD;
    float acc = 0.f;
    #pragma unroll 4
    for (int l = 0; l < LATD; l++) acc += lt[l] * lin[j * LATD + l];
    sb[idx] = acc;
}

// ---------------- generic 1x1 conv (GEMM) + fused epilogue --------------
// mode 0: y = prelu(cbn(conv))  (uses bn + sb + alpha)
// mode 1: y = bn(conv)          (uses bn only)
__global__ void conv1x1_kernel(const float* __restrict__ Wm,   // (Cout, Cin)
                               const float* __restrict__ X,    // (B, Cin, NP)
                               float* __restrict__ Y,          // (B, Cout, NP)
                               int Cin, int Cout, int NP,
                               const float* __restrict__ bn,   // (4, Cout)
                               const float* __restrict__ sb,   // (B, 2*Cout) or null
                               const float* __restrict__ alpha_ptr,
                               int mode)
{
    __shared__ float As[16][65];
    __shared__ float Bs[16][64];
    int tid = threadIdx.x;
    int b  = blockIdx.z;
    int o0 = blockIdx.y * 64;
    int p0 = blockIdx.x * 64;
    int ty = tid >> 4, tx = tid & 15;

    float acc[4][4];
    #pragma unroll
    for (int r = 0; r < 4; r++)
        #pragma unroll
        for (int c = 0; c < 4; c++) acc[r][c] = 0.f;

    const float* Xb = X + (size_t)b * Cin * NP;

    for (int k0 = 0; k0 < Cin; k0 += 16) {
        for (int i = tid; i < 1024; i += 256) {
            int oo = i >> 4, kk = i & 15;
            As[kk][oo] = Wm[(size_t)(o0 + oo) * Cin + k0 + kk];
        }
        for (int i = tid; i < 1024; i += 256) {
            int kk = i >> 6, pp = i & 63;
            Bs[kk][pp] = Xb[(size_t)(k0 + kk) * NP + p0 + pp];
        }
        __syncthreads();
        #pragma unroll
        for (int kk = 0; kk < 16; kk++) {
            float a[4], bv[4];
            #pragma unroll
            for (int r = 0; r < 4; r++) a[r] = As[kk][ty + 16 * r];
            #pragma unroll
            for (int c = 0; c < 4; c++) bv[c] = Bs[kk][tx + 16 * c];
            #pragma unroll
            for (int r = 0; r < 4; r++)
                #pragma unroll
                for (int c = 0; c < 4; c++) acc[r][c] += a[r] * bv[c];
        }
        __syncthreads();
    }

    #pragma unroll
    for (int r = 0; r < 4; r++) {
        int o = o0 + ty + 16 * r;
        float gam = bn[o], bet = bn[Cout + o], mn = bn[2 * Cout + o], vr = bn[3 * Cout + o];
        float bsc = gam * rsqrtf(vr + EPSV);
        float bbi = bet - mn * bsc;
        #pragma unroll
        for (int c = 0; c < 4; c++) {
            int p = p0 + tx + 16 * c;
            float v = acc[r][c] * bsc + bbi;
            if (mode == 0) {
                float slat = sb[b * 2 * Cout + o];
                float blat = sb[b * 2 * Cout + Cout + o];
                v = v * slat + blat;
                float alpha = *alpha_ptr;
                v = v > 0.f ? v : alpha * v;
            }
            Y[((size_t)(b * Cout + o)) * NP + p] = v;
        }
    }
}

// ---------------- fused axial attention core ----------------------------
// One block = one (bn, g) group. dim=0: attend over h (d1=w); dim=1: over w.
#define ATTN_SMEM_FLOATS (512 + 512 + 1024 + 4064 + 3 * 4160)
#define ATTN_SMEM_BYTES (ATTN_SMEM_FLOATS * 4)

__global__ void attn_kernel(const float* __restrict__ qkv,   // (B,512,64,64)
                            float* __restrict__ out,          // (B,256,64,64)
                            const float* __restrict__ rel,    // (32,127)
                            const float* __restrict__ bns,    // (4,48)
                            const float* __restrict__ bno,    // (4,512)
                            int dim)
{
    extern __shared__ float sm[];
    float* sq   = sm;             // [8][64]
    float* sk   = sq + 512;       // [8][64]
    float* sv   = sk + 512;       // [16][64]
    float* srel = sv + 1024;      // [32][127]
    float* sqe  = srel + 4064;    // [64][65]
    float* ske  = sqe + 4160;     // [64][65]
    float* ssim = ske + 4160;     // [64][65]

    int tid = threadIdx.x;
    int bn = blockIdx.x;          // 0..255
    int g  = blockIdx.y;          // 0..15
    int b  = bn >> 6, d1 = bn & 63;
    int stride_t = (dim == 0) ? 64 : 1;
    size_t base_off = (size_t)b * 512 * NP_FULL + (size_t)((dim == 0) ? d1 : d1 * 64);

    // ---- load q(8x64), k(8x64), v(16x64), rel(32x127) ----
    for (int i = tid; i < 2048; i += 256) {
        int u = i >> 6;           // 0..31
        int t = i & 63;
        float val = qkv[base_off + (size_t)(g * 32 + u) * NP_FULL + (size_t)t * stride_t];
        if (u < 8)        sq[u * 64 + t] = val;
        else if (u < 16)  sk[(u - 8) * 64 + t] = val;
        else              sv[(u - 16) * 64 + t] = val;
    }
    for (int i = tid; i < 4064; i += 256) srel[i] = rel[i];
    __syncthreads();

    // ---- phase 2: q_emb[t][j], k_emb[t][j] via on-the-fly rel gather ----
    for (int idx = tid; idx < 4096; idx += 256) {
        int t = idx >> 6, j = idx & 63;
        int p = t - j + 63;
        float aq = 0.f, ak = 0.f;
        #pragma unroll
        for (int c = 0; c < 8; c++) {
            aq += sq[c * 64 + t] * srel[c * 127 + p];
            ak += sk[c * 64 + t] * srel[(8 + c) * 127 + p];
        }
        sqe[t * 65 + j] = aq;
        ske[t * 65 + j] = ak;
    }
    __syncthreads();

    // ---- BN-sim affine scalars (channels: qk->g, q_emb->16+g, k_emb->32+g) ----
    float sA = bns[g]      * rsqrtf(bns[144 + g]      + EPSV);
    float sB = bns[16 + g] * rsqrtf(bns[144 + 16 + g] + EPSV);
    float sC = bns[32 + g] * rsqrtf(bns[144 + 32 + g] + EPSV);
    float tsum = (bns[48 + g]      - bns[96 + g]      * sA)
               + (bns[48 + 16 + g] - bns[96 + 16 + g] * sB)
               + (bns[48 + 32 + g] - bns[96 + 32 + g] * sC);

    // ---- phase 3: qk[i][j] = sum_t qe[t][i]*ke[t][j], then combine ----
    {
        int ti = tid >> 4, tj = tid & 15;
        float acc[4][4];
        #pragma unroll
        for (int u = 0; u < 4; u++)
            #pragma unroll
            for (int v = 0; v < 4; v++) acc[u][v] = 0.f;
        for (int t = 0; t < 64; t++) {
            float a[4], bv[4];
            #pragma unroll
            for (int u = 0; u < 4; u++) a[u] = sqe[t * 65 + ti + 16 * u];
            #pragma unroll
            for (int v = 0; v < 4; v++) bv[v] = ske[t * 65 + tj + 16 * v];
            #pragma unroll
            for (int u = 0; u < 4; u++)
                #pragma unroll
                for (int v = 0; v < 4; v++) acc[u][v] += a[u] * bv[v];
        }
        #pragma unroll
        for (int u = 0; u < 4; u++)
            #pragma unroll
            for (int v = 0; v < 4; v++) {
                int i = ti + 16 * u, j = tj + 16 * v;
                ssim[i * 65 + j] = sA * acc[u][v] + sB * sqe[i * 65 + j]
                                 + sC * ske[i * 65 + j] + tsum;
            }
    }
    __syncthreads();

    // ---- phase 4: row softmax (4 threads per row) ----
    {
        int r = tid >> 2, l = tid & 3;
        float m = -1e30f;
        #pragma unroll
        for (int jj = 0; jj < 16; jj++) m = fmaxf(m, ssim[r * 65 + l + 4 * jj]);
        m = fmaxf(m, __shfl_xor_sync(0xffffffffu, m, 1));
        m = fmaxf(m, __shfl_xor_sync(0xffffffffu, m, 2));
        float ssum = 0.f;
        #pragma unroll
        for (int jj = 0; jj < 16; jj++) {
            int id = r * 65 + l + 4 * jj;
            float e = __expf(ssim[id] - m);
            ssim[id] = e;
            ssum += e;
        }
        ssum += __shfl_xor_sync(0xffffffffu, ssum, 1);
        ssum += __shfl_xor_sync(0xffffffffu, ssum, 2);
        float inv = 1.f / ssum;
        #pragma unroll
        for (int jj = 0; jj < 16; jj++) ssim[r * 65 + l + 4 * jj] *= inv;
    }
    __syncthreads();

    // ---- phase 5: att / att_e, BN_out, interleaved channel sum, write ----
    {
        int i = tid & 63, cb = tid >> 6;   // cb 0..3, 4 channels each
        float acca[4] = {0.f, 0.f, 0.f, 0.f};
        float acce[4] = {0.f, 0.f, 0.f, 0.f};
        for (int j = 0; j < 64; j++) {
            float s = ssim[i * 65 + j];
            int p = i - j + 63;
            #pragma unroll
            for (int cc = 0; cc < 4; cc++) {
                int c = cb * 4 + cc;
                acca[cc] += s * sv[c * 64 + j];
                acce[cc] += s * srel[(16 + c) * 127 + p];
            }
        }
        #pragma unroll
        for (int cc = 0; cc < 4; cc++) {
            int c = cb * 4 + cc;
            int chA = g * 32 + 2 * c, chB = chA + 1;
            float sa = bno[chA] * rsqrtf(bno[1536 + chA] + EPSV);
            float ba = bno[512 + chA] - bno[1024 + chA] * sa;
            float sb2 = bno[chB] * rsqrtf(bno[1536 + chB] + EPSV);
            float bb2 = bno[512 + chB] - bno[1024 + chB] * sb2;
            float v = acca[cc] * sa + ba + acce[cc] * sb2 + bb2;
            int ch = g * 16 + c;
            size_t oidx = (dim == 0)
                ? (((size_t)(b * CO + ch) * 64 + i) * 64 + d1)
                : (((size_t)(b * CO + ch) * 64 + d1) * 64 + i);
            out[oidx] = v;
        }
    }
}

// ---------------- 2x2 average pool --------------------------------------
__global__ void pool_kernel(const float* __restrict__ in, float* __restrict__ out, int C)
{
    int idx = blockIdx.x * blockDim.x + threadIdx.x;
    int total = NB * C * NP_HALF;
    if (idx >= total) return;
    int j = idx & 31;
    int i = (idx >> 5) & 31;
    int bc = idx >> 10;
    const float* p = in + (size_t)bc * NP_FULL + (size_t)(2 * i) * 64 + 2 * j;
    out[idx] = 0.25f * (p[0] + p[1] + p[64] + p[65]);
}

// ---------------- final: cbn(conv_out) + conv_res, prelu ----------------
__global__ void final_kernel(const float* __restrict__ Wo,    // (256,256)
                             const float* __restrict__ py,    // (B,256,1024)
                             const float* __restrict__ Wr,    // (256,128)
                             const float* __restrict__ px,    // (B,128,1024)
                             float* __restrict__ out,         // (B,256,1024)
                             const float* __restrict__ bn,    // (4,256)
                             const float* __restrict__ sb,    // (B,512)
                             const float* __restrict__ alpha_ptr)
{
    __shared__ float As[16][65];
    __shared__ float Bs[16][64];
    int tid = threadIdx.x;
    int b  = blockIdx.z;
    int o0 = blockIdx.y * 64;
    int p0 = blockIdx.x * 64;
    int ty = tid >> 4, tx = tid & 15;

    float accO[4][4], accR[4][4];
    #pragma unroll
    for (int r = 0; r < 4; r++)
        #pragma unroll
        for (int c = 0; c < 4; c++) { accO[r][c] = 0.f; accR[r][c] = 0.f; }

    // pass 1: w_out @ pooled y3 (K=256)
    const float* Xb = py + (size_t)b * CO * NP_HALF;
    for (int k0 = 0; k0 < CO; k0 += 16) {
        for (int i = tid; i < 1024; i += 256) {
            int oo = i >> 4, kk = i & 15;
            As[kk][oo] = Wo[(size_t)(o0 + oo) * CO + k0 + kk];
        }
        for (int i = tid; i < 1024; i += 256) {
            int kk = i >> 6, pp = i & 63;
            Bs[kk][pp] = Xb[(size_t)(k0 + kk) * NP_HALF + p0 + pp];
        }
        __syncthreads();
        #pragma unroll
        for (int kk = 0; kk < 16; kk++) {
            float a[4], bv[4];
            #pragma unroll
            for (int r = 0; r < 4; r++) a[r] = As[kk][ty + 16 * r];
            #pragma unroll
            for (int c = 0; c < 4; c++) bv[c] = Bs[kk][tx + 16 * c];
            #pragma unroll
            for (int r = 0; r < 4; r++)
                #pragma unroll
                for (int c = 0; c < 4; c++) accO[r][c] += a[r] * bv[c];
        }
        __syncthreads();
    }

    // pass 2: w_res @ pooled x (K=128)
    const float* Xr = px + (size_t)b * CINC * NP_HALF;
    for (int k0 = 0; k0 < CINC; k0 += 16) {
        for (int i = tid; i < 1024; i += 256) {
            int oo = i >> 4, kk = i & 15;
            As[kk][oo] = Wr[(size_t)(o0 + oo) * CINC + k0 + kk];
        }
        for (int i = tid; i < 1024; i += 256) {
            int kk = i >> 6, pp = i & 63;
            Bs[kk][pp] = Xr[(size_t)(k0 + kk) * NP_HALF + p0 + pp];
        }
        __syncthreads();
        #pragma unroll
        for (int kk = 0; kk < 16; kk++) {
            float a[4], bv[4];
            #pragma unroll
            for (int r = 0; r < 4; r++) a[r] = As[kk][ty + 16 * r];
            #pragma unroll
            for (int c = 0; c < 4; c++) bv[c] = Bs[kk][tx + 16 * c];
            #pragma unroll
            for (int r = 0; r < 4; r++)
                #pragma unroll
                for (int c = 0; c < 4; c++) accR[r][c] += a[r] * bv[c];
        }
        __syncthreads();
    }

    float alpha = *alpha_ptr;
    #pragma unroll
    for (int r = 0; r < 4; r++) {
        int o = o0 + ty + 16 * r;
        float gam = bn[o], bet = bn[CO + o], mn = bn[2 * CO + o], vr = bn[3 * CO + o];
        float bsc = gam * rsqrtf(vr + EPSV);
        float bbi = bet - mn * bsc;
        float slat = sb[b * 512 + o];
        float blat = sb[b * 512 + 256 + o];
        #pragma unroll
        for (int c = 0; c < 4; c++) {
            int p = p0 + tx + 16 * c;
            float v = (accO[r][c] * bsc + bbi) * slat + blat + accR[r][c];
            v = v > 0.f ? v : alpha * v;
            out[((size_t)(b * CO + o)) * NP_HALF + p] = v;
        }
    }
}

// ---------------- launcher ----------------------------------------------
extern "C" void kernel_launch(void* const* d_in, const int* in_sizes, int n_in,
                              void* d_out, int out_size)
{
    const float* x         = (const float*)d_in[0];
    const float* latent    = (const float*)d_in[1];
    const float* w_in      = (const float*)d_in[2];
    const float* bn_in     = (const float*)d_in[3];
    const float* lin_in    = (const float*)d_in[4];
    const float* alpha_in  = (const float*)d_in[5];
    const float* a0_wqkv   = (const float*)d_in[6];
    const float* a0_bn_qkv = (const float*)d_in[7];
    const float* a0_bn_sim = (const float*)d_in[8];
    const float* a0_bn_out = (const float*)d_in[9];
    const float* a0_rel    = (const float*)d_in[10];
    const float* a1_wqkv   = (const float*)d_in[11];
    const float* a1_bn_qkv = (const float*)d_in[12];
    const float* a1_bn_sim = (const float*)d_in[13];
    const float* a1_bn_out = (const float*)d_in[14];
    const float* a1_rel    = (const float*)d_in[15];
    const float* w_out     = (const float*)d_in[16];
    const float* bn_out    = (const float*)d_in[17];
    const float* lin_out   = (const float*)d_in[18];
    const float* w_res     = (const float*)d_in[19];
    const float* alpha_fin = (const float*)d_in[20];
    float* out = (float*)d_out;

    float *yb, *qkvb, *pyb, *pxb, *sbb;
    cudaGetSymbolAddress((void**)&yb,   g_y);
    cudaGetSymbolAddress((void**)&qkvb, g_qkv);
    cudaGetSymbolAddress((void**)&pyb,  g_py);
    cudaGetSymbolAddress((void**)&pxb,  g_px);
    cudaGetSymbolAddress((void**)&sbb,  g_sb);

    cudaFuncSetAttribute(attn_kernel, cudaFuncAttributeMaxDynamicSharedMemorySize,
                         ATTN_SMEM_BYTES);

    // 1. latent-conditioned scale/bias
    sb_kernel<<<16, 256>>>(latent, lin_in, lin_out, sbb);

    // 2. y1 = prelu(cbn(conv1x1(w_in, x)))
    {
        dim3 g(NP_FULL / 64, CO / 64, NB);
        conv1x1_kernel<<<g, 256>>>(w_in, x, yb, CINC, CO, NP_FULL,
                                   bn_in, sbb, alpha_in, 0);
    }

    // 3. axial-0: qkv conv + BN, then fused attention over H
    {
        dim3 g(NP_FULL / 64, (2 * CO) / 64, NB);
        conv1x1_kernel<<<g, 256>>>(a0_wqkv, yb, qkvb, CO, 2 * CO, NP_FULL,
                                   a0_bn_qkv, nullptr, nullptr, 1);
        dim3 ga(256, NG);
        attn_kernel<<<ga, 256, ATTN_SMEM_BYTES>>>(qkvb, yb, a0_rel,
                                                  a0_bn_sim, a0_bn_out, 0);
    }

    // 4. axial-1: qkv conv + BN, then fused attention over W
    {
        dim3 g(NP_FULL / 64, (2 * CO) / 64, NB);
        conv1x1_kernel<<<g, 256>>>(a1_wqkv, yb, qkvb, CO, 2 * CO, NP_FULL,
                                   a1_bn_qkv, nullptr, nullptr, 1);
        dim3 ga(256, NG);
        attn_kernel<<<ga, 256, ATTN_SMEM_BYTES>>>(qkvb, yb, a1_rel,
                                                  a1_bn_sim, a1_bn_out, 1);
    }

    // 5. pool both branches (1x1 conv commutes with avg-pool)
    pool_kernel<<<(NB * CO * NP_HALF + 255) / 256, 256>>>(yb, pyb, CO);
    pool_kernel<<<(NB * CINC * NP_HALF + 255) / 256, 256>>>(x, pxb, CINC);

    // 6. out = prelu(cbn(conv(w_out, py)) + conv(w_res, px))
    {
        dim3 g(NP_HALF / 64, CO / 64, NB);
        final_kernel<<<g, 256>>>(w_out, pyb, w_res, pxb, out,
                                 bn_out, sbb + 2048, alpha_fin);
    }
}

// round 2
// speedup vs baseline: 1.2937x; 1.2937x over previous
#include <cuda_runtime.h>
#include <math.h>

#define EPSV 1e-5f

// Problem dims
#define NB   4
#define CINC 128
#define CO   256
#define LATD 256
#define NG   16
#define NP_FULL 4096     // 64*64
#define NP_HALF 1024     // 32*32

// ---------------- scratch (device globals; no allocation) ----------------
__device__ float g_y[NB * CO * NP_FULL];
__device__ float g_qkv[NB * 2 * CO * NP_FULL];
__device__ float g_py[NB * CO * NP_HALF];
__device__ float g_px[NB * CINC * NP_HALF];
__device__ float g_sb[4096];

// ---------------- latent -> per-(b,ch) scale/bias -----------------------
__global__ void sb_kernel(const float* __restrict__ latent,
                          const float* __restrict__ lin_in,
                          const float* __restrict__ lin_out,
                          float* __restrict__ sb)
{
    int idx = blockIdx.x * blockDim.x + threadIdx.x;
    if (idx >= 4096) return;
    int which = idx >> 11;
    int b = (idx >> 9) & 3;
    int j = idx & 511;
    const float* lin = which ? lin_out : lin_in;
    const float* lt = latent + b * LATD;
    float acc = 0.f;
    #pragma unroll 4
    for (int l = 0; l < LATD; l++) acc += lt[l] * lin[j * LATD + l];
    sb[idx] = acc;
}

// ---------------- SGEMM 1x1 conv: 128x128 tile, 8x8 per thread ----------
// mode 0: y = prelu(cbn(conv));  mode 1: y = bn(conv)
__global__ __launch_bounds__(256)
void conv1x1_kernel(const float* __restrict__ Wm,   // (Cout, Cin)
                    const float* __restrict__ X,    // (B, Cin, NP)
                    float* __restrict__ Y,          // (B, Cout, NP)
                    int Cin, int Cout, int NP,
                    const float* __restrict__ bn,
                    const float* __restrict__ sb,
                    const float* __restrict__ alpha_ptr,
                    int mode)
{
    __shared__ float As[8][128];
    __shared__ float Bs[8][128];
    int tid = threadIdx.x;
    int b  = blockIdx.z;
    int o0 = blockIdx.y * 128;
    int p0 = blockIdx.x * 128;
    const float* Xb = X + (size_t)b * Cin * NP;

    int arow = tid >> 1, akq = (tid & 1) * 4;
    int brow = tid >> 5, bcol = (tid & 31) * 4;
    int tx = tid & 15, ty = tid >> 4;

    float4 pa = *(const float4*)&Wm[(size_t)(o0 + arow) * Cin + akq];
    float4 pb = *(const float4*)&Xb[(size_t)brow * NP + p0 + bcol];

    float acc[8][8];
    #pragma unroll
    for (int r = 0; r < 8; r++)
        #pragma unroll
        for (int c = 0; c < 8; c++) acc[r][c] = 0.f;

    int nk = Cin >> 3;
    for (int kc = 0; kc < nk; kc++) {
        As[akq + 0][arow] = pa.x;
        As[akq + 1][arow] = pa.y;
        As[akq + 2][arow] = pa.z;
        As[akq + 3][arow] = pa.w;
        *(float4*)&Bs[brow][bcol] = pb;
        __syncthreads();
        if (kc + 1 < nk) {
            int k0 = (kc + 1) << 3;
            pa = *(const float4*)&Wm[(size_t)(o0 + arow) * Cin + k0 + akq];
            pb = *(const float4*)&Xb[(size_t)(k0 + brow) * NP + p0 + bcol];
        }
        #pragma unroll
        for (int kk = 0; kk < 8; kk++) {
            float4 a0 = *(const float4*)&As[kk][ty * 4];
            float4 a1 = *(const float4*)&As[kk][ty * 4 + 64];
            float4 b0 = *(const float4*)&Bs[kk][tx * 4];
            float4 b1 = *(const float4*)&Bs[kk][tx * 4 + 64];
            float av[8] = {a0.x, a0.y, a0.z, a0.w, a1.x, a1.y, a1.z, a1.w};
            float bv[8] = {b0.x, b0.y, b0.z, b0.w, b1.x, b1.y, b1.z, b1.w};
            #pragma unroll
            for (int r = 0; r < 8; r++)
                #pragma unroll
                for (int c = 0; c < 8; c++)
                    acc[r][c] += av[r] * bv[c];
        }
        __syncthreads();
    }

    float alpha = (mode == 0) ? *alpha_ptr : 0.f;
    #pragma unroll
    for (int r = 0; r < 8; r++) {
        int m = (r < 4) ? (ty * 4 + r) : (64 + ty * 4 + r - 4);
        int o = o0 + m;
        float bsc = bn[o] * rsqrtf(bn[3 * Cout + o] + EPSV);
        float bbi = bn[Cout + o] - bn[2 * Cout + o] * bsc;
        float slat = 1.f, blat = 0.f;
        if (mode == 0) {
            slat = sb[b * 2 * Cout + o];
            blat = sb[b * 2 * Cout + Cout + o];
        }
        #pragma unroll
        for (int cq = 0; cq < 2; cq++) {
            float4 v;
            float vv[4];
            #pragma unroll
            for (int cc = 0; cc < 4; cc++) {
                float val = acc[r][cq * 4 + cc] * bsc + bbi;
                if (mode == 0) {
                    val = val * slat + blat;
                    val = val > 0.f ? val : alpha * val;
                }
                vv[cc] = val;
            }
            v.x = vv[0]; v.y = vv[1]; v.z = vv[2]; v.w = vv[3];
            int p = p0 + tx * 4 + cq * 64;
            *(float4*)&Y[((size_t)(b * Cout + o)) * NP + p] = v;
        }
    }
}

// ---------------- fused axial attention core ----------------------------
// smem layout (floats):
//   sqkT : [64][16]  (q c=0..7, k c=8..15)     1024
//   svT  : [64][16]                            1024
//   srelT: [127][36] (pad 36)                  4576
//   sqe  : [64][64]                            4096
//   ske  : [64][64]                            4096
//   ssim : [64][68]                            4352
#define OFF_SQK  0
#define OFF_SV   1024
#define OFF_REL  2048
#define OFF_QE   6624
#define OFF_KE   10720
#define OFF_SIM  14816
#define ATTN_SMEM_FLOATS 19168
#define ATTN_SMEM_BYTES (ATTN_SMEM_FLOATS * 4)

__global__ __launch_bounds__(256)
void attn_kernel(const float* __restrict__ qkv,   // (B,512,64,64)
                 float* __restrict__ out,          // (B,256,64,64)
                 const float* __restrict__ rel,    // (32,127)
                 const float* __restrict__ bns,    // (4,48)
                 const float* __restrict__ bno,    // (4,512)
                 int dim)
{
    extern __shared__ float sm[];
    float* sqkT = sm + OFF_SQK;
    float* svT  = sm + OFF_SV;
    float* srelT= sm + OFF_REL;
    float* sqe  = sm + OFF_QE;
    float* ske  = sm + OFF_KE;
    float* ssim = sm + OFF_SIM;

    int tid = threadIdx.x;
    int bn = blockIdx.x;
    int g  = blockIdx.y;
    int b  = bn >> 6, d1 = bn & 63;
    int stride_t = (dim == 0) ? 64 : 1;
    size_t base_off = (size_t)b * 512 * NP_FULL + (size_t)((dim == 0) ? d1 : d1 * 64);

    // ---- phase 1: load qkv transposed + rel transposed ----
    for (int i = tid; i < 2048; i += 256) {
        int u = i >> 6;
        int t = i & 63;
        float val = qkv[base_off + (size_t)(g * 32 + u) * NP_FULL + (size_t)t * stride_t];
        if (u < 16) sqkT[t * 16 + u] = val;
        else        svT[t * 16 + (u - 16)] = val;
    }
    for (int i = tid; i < 4064; i += 256) {
        int c = i / 127;
        int p = i - c * 127;
        srelT[p * 36 + c] = rel[i];
    }
    __syncthreads();

    // ---- phase 2: q_emb[t][j], k_emb[t][j] ----
    {
        int jj = tid & 63, tb = tid >> 6;
        #pragma unroll 4
        for (int tt = 0; tt < 16; tt++) {
            int t = tb * 16 + tt;
            const float4 q0 = *(const float4*)&sqkT[t * 16];
            const float4 q1 = *(const float4*)&sqkT[t * 16 + 4];
            const float4 k0 = *(const float4*)&sqkT[t * 16 + 8];
            const float4 k1 = *(const float4*)&sqkT[t * 16 + 12];
            int p = t - jj + 63;
            const float4 rq0 = *(const float4*)&srelT[p * 36];
            const float4 rq1 = *(const float4*)&srelT[p * 36 + 4];
            const float4 rk0 = *(const float4*)&srelT[p * 36 + 8];
            const float4 rk1 = *(const float4*)&srelT[p * 36 + 12];
            float aq = q0.x*rq0.x + q0.y*rq0.y + q0.z*rq0.z + q0.w*rq0.w
                     + q1.x*rq1.x + q1.y*rq1.y + q1.z*rq1.z + q1.w*rq1.w;
            float ak = k0.x*rk0.x + k0.y*rk0.y + k0.z*rk0.z + k0.w*rk0.w
                     + k1.x*rk1.x + k1.y*rk1.y + k1.z*rk1.z + k1.w*rk1.w;
            sqe[t * 64 + jj] = aq;
            ske[t * 64 + jj] = ak;
        }
    }
    __syncthreads();

    // ---- BN-sim affine scalars ----
    float sA = bns[g]      * rsqrtf(bns[144 + g]      + EPSV);
    float sB = bns[16 + g] * rsqrtf(bns[144 + 16 + g] + EPSV);
    float sC = bns[32 + g] * rsqrtf(bns[144 + 32 + g] + EPSV);
    float tsum = (bns[48 + g]      - bns[96 + g]      * sA)
               + (bns[48 + 16 + g] - bns[96 + 16 + g] * sB)
               + (bns[48 + 32 + g] - bns[96 + 32 + g] * sC);

    // ---- phase 3: qk[i][j] = sum_t qe[t][i]*ke[t][j]; combine; write ssim ----
    {
        int ti = tid & 15, tj = tid >> 4;
        float acc[4][4];
        #pragma unroll
        for (int u = 0; u < 4; u++)
            #pragma unroll
            for (int v = 0; v < 4; v++) acc[u][v] = 0.f;
        #pragma unroll 4
        for (int t = 0; t < 64; t++) {
            float4 qa = *(const float4*)&sqe[t * 64 + ti * 4];
            float4 kb = *(const float4*)&ske[t * 64 + tj * 4];
            float av[4] = {qa.x, qa.y, qa.z, qa.w};
            float bv[4] = {kb.x, kb.y, kb.z, kb.w};
            #pragma unroll
            for (int u = 0; u < 4; u++)
                #pragma unroll
                for (int v = 0; v < 4; v++) acc[u][v] += av[u] * bv[v];
        }
        #pragma unroll
        for (int u = 0; u < 4; u++) {
            int i = ti * 4 + u;
            float4 qe_i = *(const float4*)&sqe[i * 64 + tj * 4];
            float4 ke_i = *(const float4*)&ske[i * 64 + tj * 4];
            float qv[4] = {qe_i.x, qe_i.y, qe_i.z, qe_i.w};
            float kv[4] = {ke_i.x, ke_i.y, ke_i.z, ke_i.w};
            float4 o4;
            float ov[4];
            #pragma unroll
            for (int v = 0; v < 4; v++)
                ov[v] = sA * acc[u][v] + sB * qv[v] + sC * kv[v] + tsum;
            o4.x = ov[0]; o4.y = ov[1]; o4.z = ov[2]; o4.w = ov[3];
            *(float4*)&ssim[i * 68 + tj * 4] = o4;
        }
    }
    __syncthreads();

    // ---- phase 4: row softmax (4 threads per row) ----
    {
        int r = tid >> 2, l = tid & 3;
        float m = -1e30f;
        #pragma unroll
        for (int jj = 0; jj < 16; jj++) m = fmaxf(m, ssim[r * 68 + l + 4 * jj]);
        m = fmaxf(m, __shfl_xor_sync(0xffffffffu, m, 1));
        m = fmaxf(m, __shfl_xor_sync(0xffffffffu, m, 2));
        float ssum = 0.f;
        #pragma unroll
        for (int jj = 0; jj < 16; jj++) {
            int id = r * 68 + l + 4 * jj;
            float e = __expf(ssim[id] - m);
            ssim[id] = e;
            ssum += e;
        }
        ssum += __shfl_xor_sync(0xffffffffu, ssum, 1);
        ssum += __shfl_xor_sync(0xffffffffu, ssum, 2);
        float inv = 1.f / ssum;
        #pragma unroll
        for (int jj = 0; jj < 16; jj++) ssim[r * 68 + l + 4 * jj] *= inv;
    }
    __syncthreads();

    // ---- phase 5: att / att_e, BN_out, channel-pair sum, write ----
    {
        int i = tid & 63, cb = tid >> 6;   // 4 channels per thread
        float acca[4] = {0.f, 0.f, 0.f, 0.f};
        float acce[4] = {0.f, 0.f, 0.f, 0.f};
        #pragma unroll 4
        for (int j0 = 0; j0 < 64; j0 += 4) {
            float4 s4 = *(const float4*)&ssim[i * 68 + j0];
            float sarr[4] = {s4.x, s4.y, s4.z, s4.w};
            #pragma unroll
            for (int e = 0; e < 4; e++) {
                int j = j0 + e;
                float s = sarr[e];
                float4 v4 = *(const float4*)&svT[j * 16 + cb * 4];
                float4 r4 = *(const float4*)&srelT[(i - j + 63) * 36 + 16 + cb * 4];
                acca[0] += s * v4.x;  acca[1] += s * v4.y;
                acca[2] += s * v4.z;  acca[3] += s * v4.w;
                acce[0] += s * r4.x;  acce[1] += s * r4.y;
                acce[2] += s * r4.z;  acce[3] += s * r4.w;
            }
        }
        #pragma unroll
        for (int cc = 0; cc < 4; cc++) {
            int c = cb * 4 + cc;
            int chA = g * 32 + 2 * c, chB = chA + 1;
            float sa = bno[chA] * rsqrtf(bno[1536 + chA] + EPSV);
            float ba = bno[512 + chA] - bno[1024 + chA] * sa;
            float sb2 = bno[chB] * rsqrtf(bno[1536 + chB] + EPSV);
            float bb2 = bno[512 + chB] - bno[1024 + chB] * sb2;
            float v = acca[cc] * sa + ba + acce[cc] * sb2 + bb2;
            int ch = g * 16 + c;
            size_t oidx = (dim == 0)
                ? (((size_t)(b * CO + ch) * 64 + i) * 64 + d1)
                : (((size_t)(b * CO + ch) * 64 + d1) * 64 + i);
            out[oidx] = v;
        }
    }
}

// ---------------- 2x2 average pool --------------------------------------
__global__ void pool_kernel(const float* __restrict__ in, float* __restrict__ out, int C)
{
    int idx = blockIdx.x * blockDim.x + threadIdx.x;
    int total = NB * C * NP_HALF;
    if (idx >= total) return;
    int j = idx & 31;
    int i = (idx >> 5) & 31;
    int bc = idx >> 10;
    const float* p = in + (size_t)bc * NP_FULL + (size_t)(2 * i) * 64 + 2 * j;
    out[idx] = 0.25f * (p[0] + p[1] + p[64] + p[65]);
}

// ---------------- final: cbn(conv_out) + conv_res, prelu ----------------
__global__ void final_kernel(const float* __restrict__ Wo,
                             const float* __restrict__ py,
                             const float* __restrict__ Wr,
                             const float* __restrict__ px,
                             float* __restrict__ out,
                             const float* __restrict__ bn,
                             const float* __restrict__ sb,
                             const float* __restrict__ alpha_ptr)
{
    __shared__ float As[16][65];
    __shared__ float Bs[16][64];
    int tid = threadIdx.x;
    int b  = blockIdx.z;
    int o0 = blockIdx.y * 64;
    int p0 = blockIdx.x * 64;
    int ty = tid >> 4, tx = tid & 15;

    float accO[4][4], accR[4][4];
    #pragma unroll
    for (int r = 0; r < 4; r++)
        #pragma unroll
        for (int c = 0; c < 4; c++) { accO[r][c] = 0.f; accR[r][c] = 0.f; }

    const float* Xb = py + (size_t)b * CO * NP_HALF;
    for (int k0 = 0; k0 < CO; k0 += 16) {
        for (int i = tid; i < 1024; i += 256) {
            int oo = i >> 4, kk = i & 15;
            As[kk][oo] = Wo[(size_t)(o0 + oo) * CO + k0 + kk];
        }
        for (int i = tid; i < 1024; i += 256) {
            int kk = i >> 6, pp = i & 63;
            Bs[kk][pp] = Xb[(size_t)(k0 + kk) * NP_HALF + p0 + pp];
        }
        __syncthreads();
        #pragma unroll
        for (int kk = 0; kk < 16; kk++) {
            float a[4], bv[4];
            #pragma unroll
            for (int r = 0; r < 4; r++) a[r] = As[kk][ty + 16 * r];
            #pragma unroll
            for (int c = 0; c < 4; c++) bv[c] = Bs[kk][tx + 16 * c];
            #pragma unroll
            for (int r = 0; r < 4; r++)
                #pragma unroll
                for (int c = 0; c < 4; c++) accO[r][c] += a[r] * bv[c];
        }
        __syncthreads();
    }

    const float* Xr = px + (size_t)b * CINC * NP_HALF;
    for (int k0 = 0; k0 < CINC; k0 += 16) {
        for (int i = tid; i < 1024; i += 256) {
            int oo = i >> 4, kk = i & 15;
            As[kk][oo] = Wr[(size_t)(o0 + oo) * CINC + k0 + kk];
        }
        for (int i = tid; i < 1024; i += 256) {
            int kk = i >> 6, pp = i & 63;
            Bs[kk][pp] = Xr[(size_t)(k0 + kk) * NP_HALF + p0 + pp];
        }
        __syncthreads();
        #pragma unroll
        for (int kk = 0; kk < 16; kk++) {
            float a[4], bv[4];
            #pragma unroll
            for (int r = 0; r < 4; r++) a[r] = As[kk][ty + 16 * r];
            #pragma unroll
            for (int c = 0; c < 4; c++) bv[c] = Bs[kk][tx + 16 * c];
            #pragma unroll
            for (int r = 0; r < 4; r++)
                #pragma unroll
                for (int c = 0; c < 4; c++) accR[r][c] += a[r] * bv[c];
        }
        __syncthreads();
    }

    float alpha = *alpha_ptr;
    #pragma unroll
    for (int r = 0; r < 4; r++) {
        int o = o0 + ty + 16 * r;
        float bsc = bn[o] * rsqrtf(bn[3 * CO + o] + EPSV);
        float bbi = bn[CO + o] - bn[2 * CO + o] * bsc;
        float slat = sb[b * 512 + o];
        float blat = sb[b * 512 + 256 + o];
        #pragma unroll
        for (int c = 0; c < 4; c++) {
            int p = p0 + tx + 16 * c;
            float v = (accO[r][c] * bsc + bbi) * slat + blat + accR[r][c];
            v = v > 0.f ? v : alpha * v;
            out[((size_t)(b * CO + o)) * NP_HALF + p] = v;
        }
    }
}

// ---------------- launcher ----------------------------------------------
extern "C" void kernel_launch(void* const* d_in, const int* in_sizes, int n_in,
                              void* d_out, int out_size)
{
    const float* x         = (const float*)d_in[0];
    const float* latent    = (const float*)d_in[1];
    const float* w_in      = (const float*)d_in[2];
    const float* bn_in     = (const float*)d_in[3];
    const float* lin_in    = (const float*)d_in[4];
    const float* alpha_in  = (const float*)d_in[5];
    const float* a0_wqkv   = (const float*)d_in[6];
    const float* a0_bn_qkv = (const float*)d_in[7];
    const float* a0_bn_sim = (const float*)d_in[8];
    const float* a0_bn_out = (const float*)d_in[9];
    const float* a0_rel    = (const float*)d_in[10];
    const float* a1_wqkv   = (const float*)d_in[11];
    const float* a1_bn_qkv = (const float*)d_in[12];
    const float* a1_bn_sim = (const float*)d_in[13];
    const float* a1_bn_out = (const float*)d_in[14];
    const float* a1_rel    = (const float*)d_in[15];
    const float* w_out     = (const float*)d_in[16];
    const float* bn_out    = (const float*)d_in[17];
    const float* lin_out   = (const float*)d_in[18];
    const float* w_res     = (const float*)d_in[19];
    const float* alpha_fin = (const float*)d_in[20];
    float* out = (float*)d_out;

    float *yb, *qkvb, *pyb, *pxb, *sbb;
    cudaGetSymbolAddress((void**)&yb,   g_y);
    cudaGetSymbolAddress((void**)&qkvb, g_qkv);
    cudaGetSymbolAddress((void**)&pyb,  g_py);
    cudaGetSymbolAddress((void**)&pxb,  g_px);
    cudaGetSymbolAddress((void**)&sbb,  g_sb);

    cudaFuncSetAttribute(attn_kernel, cudaFuncAttributeMaxDynamicSharedMemorySize,
                         ATTN_SMEM_BYTES);

    // 1. latent-conditioned scale/bias
    sb_kernel<<<16, 256>>>(latent, lin_in, lin_out, sbb);

    // 2. y1 = prelu(cbn(conv1x1(w_in, x)))
    {
        dim3 g(NP_FULL / 128, CO / 128, NB);
        conv1x1_kernel<<<g, 256>>>(w_in, x, yb, CINC, CO, NP_FULL,
                                   bn_in, sbb, alpha_in, 0);
    }

    // 3. axial-0
    {
        dim3 g(NP_FULL / 128, (2 * CO) / 128, NB);
        conv1x1_kernel<<<g, 256>>>(a0_wqkv, yb, qkvb, CO, 2 * CO, NP_FULL,
                                   a0_bn_qkv, nullptr, nullptr, 1);
        dim3 ga(256, NG);
        attn_kernel<<<ga, 256, ATTN_SMEM_BYTES>>>(qkvb, yb, a0_rel,
                                                  a0_bn_sim, a0_bn_out, 0);
    }

    // 4. axial-1
    {
        dim3 g(NP_FULL / 128, (2 * CO) / 128, NB);
        conv1x1_kernel<<<g, 256>>>(a1_wqkv, yb, qkvb, CO, 2 * CO, NP_FULL,
                                   a1_bn_qkv, nullptr, nullptr, 1);
        dim3 ga(256, NG);
        attn_kernel<<<ga, 256, ATTN_SMEM_BYTES>>>(qkvb, yb, a1_rel,
                                                  a1_bn_sim, a1_bn_out, 1);
    }

    // 5. pools
    pool_kernel<<<(NB * CO * NP_HALF + 255) / 256, 256>>>(yb, pyb, CO);
    pool_kernel<<<(NB * CINC * NP_HALF + 255) / 256, 256>>>(x, pxb, CINC);

    // 6. final
    {
        dim3 g(NP_HALF / 64, CO / 64, NB);
        final_kernel<<<g, 256>>>(w_out, pyb, w_res, pxb, out,
                                 bn_out, sbb + 2048, alpha_fin);
    }
}

// round 3
// speedup vs baseline: 1.3419x; 1.0372x over previous
#include <cuda_runtime.h>
#include <math.h>

#define EPSV 1e-5f

// Problem dims
#define NB   4
#define CINC 128
#define CO   256
#define LATD 256
#define NG   16
#define NP_FULL 4096     // 64*64
#define NP_HALF 1024     // 32*32

// ---------------- scratch (device globals; no allocation) ----------------
__device__ float g_y[NB * CO * NP_FULL];
__device__ float g_qkv[NB * 2 * CO * NP_FULL];
__device__ float g_py[NB * CO * NP_HALF];
__device__ float g_px[NB * CINC * NP_HALF];
__device__ float g_sb[4096];

// ---------------- latent -> per-(b,ch) scale/bias -----------------------
__global__ void sb_kernel(const float* __restrict__ latent,
                          const float* __restrict__ lin_in,
                          const float* __restrict__ lin_out,
                          float* __restrict__ sb)
{
    int idx = blockIdx.x * blockDim.x + threadIdx.x;
    if (idx >= 4096) return;
    int which = idx >> 11;
    int b = (idx >> 9) & 3;
    int j = idx & 511;
    const float* lin = which ? lin_out : lin_in;
    const float* lt = latent + b * LATD;
    float acc = 0.f;
    #pragma unroll 4
    for (int l = 0; l < LATD; l++) acc += lt[l] * lin[j * LATD + l];
    sb[idx] = acc;
}

// ---------------- SGEMM 1x1 conv: 128x128 tile, 8x8 per thread ----------
// mode 0: y = prelu(cbn(conv));  mode 1: y = bn(conv)
__global__ __launch_bounds__(256)
void conv1x1_kernel(const float* __restrict__ Wm,   // (Cout, Cin)
                    const float* __restrict__ X,    // (B, Cin, NP)
                    float* __restrict__ Y,          // (B, Cout, NP)
                    int Cin, int Cout, int NP,
                    const float* __restrict__ bn,
                    const float* __restrict__ sb,
                    const float* __restrict__ alpha_ptr,
                    int mode)
{
    __shared__ float As[8][128];
    __shared__ float Bs[8][128];
    int tid = threadIdx.x;
    int b  = blockIdx.z;
    int o0 = blockIdx.y * 128;
    int p0 = blockIdx.x * 128;
    const float* Xb = X + (size_t)b * Cin * NP;

    int arow = tid >> 1, akq = (tid & 1) * 4;
    int brow = tid >> 5, bcol = (tid & 31) * 4;
    int tx = tid & 15, ty = tid >> 4;

    float4 pa = *(const float4*)&Wm[(size_t)(o0 + arow) * Cin + akq];
    float4 pb = *(const float4*)&Xb[(size_t)brow * NP + p0 + bcol];

    float acc[8][8];
    #pragma unroll
    for (int r = 0; r < 8; r++)
        #pragma unroll
        for (int c = 0; c < 8; c++) acc[r][c] = 0.f;

    int nk = Cin >> 3;
    for (int kc = 0; kc < nk; kc++) {
        As[akq + 0][arow] = pa.x;
        As[akq + 1][arow] = pa.y;
        As[akq + 2][arow] = pa.z;
        As[akq + 3][arow] = pa.w;
        *(float4*)&Bs[brow][bcol] = pb;
        __syncthreads();
        if (kc + 1 < nk) {
            int k0 = (kc + 1) << 3;
            pa = *(const float4*)&Wm[(size_t)(o0 + arow) * Cin + k0 + akq];
            pb = *(const float4*)&Xb[(size_t)(k0 + brow) * NP + p0 + bcol];
        }
        #pragma unroll
        for (int kk = 0; kk < 8; kk++) {
            float4 a0 = *(const float4*)&As[kk][ty * 4];
            float4 a1 = *(const float4*)&As[kk][ty * 4 + 64];
            float4 b0 = *(const float4*)&Bs[kk][tx * 4];
            float4 b1 = *(const float4*)&Bs[kk][tx * 4 + 64];
            float av[8] = {a0.x, a0.y, a0.z, a0.w, a1.x, a1.y, a1.z, a1.w};
            float bv[8] = {b0.x, b0.y, b0.z, b0.w, b1.x, b1.y, b1.z, b1.w};
            #pragma unroll
            for (int r = 0; r < 8; r++)
                #pragma unroll
                for (int c = 0; c < 8; c++)
                    acc[r][c] += av[r] * bv[c];
        }
        __syncthreads();
    }

    float alpha = (mode == 0) ? *alpha_ptr : 0.f;
    #pragma unroll
    for (int r = 0; r < 8; r++) {
        int m = (r < 4) ? (ty * 4 + r) : (64 + ty * 4 + r - 4);
        int o = o0 + m;
        float bsc = bn[o] * rsqrtf(bn[3 * Cout + o] + EPSV);
        float bbi = bn[Cout + o] - bn[2 * Cout + o] * bsc;
        float slat = 1.f, blat = 0.f;
        if (mode == 0) {
            slat = sb[b * 2 * Cout + o];
            blat = sb[b * 2 * Cout + Cout + o];
        }
        #pragma unroll
        for (int cq = 0; cq < 2; cq++) {
            float4 v;
            float vv[4];
            #pragma unroll
            for (int cc = 0; cc < 4; cc++) {
                float val = acc[r][cq * 4 + cc] * bsc + bbi;
                if (mode == 0) {
                    val = val * slat + blat;
                    val = val > 0.f ? val : alpha * val;
                }
                vv[cc] = val;
            }
            v.x = vv[0]; v.y = vv[1]; v.z = vv[2]; v.w = vv[3];
            int p = p0 + tx * 4 + cq * 64;
            *(float4*)&Y[((size_t)(b * Cout + o)) * NP + p] = v;
        }
    }
}

// ---------------- fused axial attention core ----------------------------
// smem layout (floats):
//   sq2  : [16][64]  (q c=0..7 rows, k c=8..15 rows; t contiguous)   1024
//   svT  : [64][16]                                                  1024
//   srel : [32][127] row-major, unpadded (scalar reads only)         4064
//   sqe  : [64][64]                                                  4096
//   ske  : [64][64]                                                  4096
//   ssim : [64][68]                                                  4352
#define OFF_SQ2  0
#define OFF_SV   1024
#define OFF_REL  2048
#define OFF_QE   6112
#define OFF_KE   10208
#define OFF_SIM  14304
#define ATTN_SMEM_FLOATS 18656
#define ATTN_SMEM_BYTES (ATTN_SMEM_FLOATS * 4)

__global__ __launch_bounds__(256)
void attn_kernel(const float* __restrict__ qkv,   // (B,512,64,64)
                 float* __restrict__ out,          // (B,256,64,64)
                 const float* __restrict__ rel,    // (32,127)
                 const float* __restrict__ bns,    // (4,48)
                 const float* __restrict__ bno,    // (4,512)
                 int dim)
{
    extern __shared__ float sm[];
    float* sq2  = sm + OFF_SQ2;
    float* svT  = sm + OFF_SV;
    float* srel = sm + OFF_REL;
    float* sqe  = sm + OFF_QE;
    float* ske  = sm + OFF_KE;
    float* ssim = sm + OFF_SIM;

    int tid = threadIdx.x;
    int bn = blockIdx.x;
    int g  = blockIdx.y;
    int b  = bn >> 6, d1 = bn & 63;
    int stride_t = (dim == 0) ? 64 : 1;
    size_t base_off = (size_t)b * 512 * NP_FULL + (size_t)((dim == 0) ? d1 : d1 * 64);

    // ---- phase 1: load q/k in [c][t], v in [t][c], rel row-major ----
    for (int i = tid; i < 2048; i += 256) {
        int u = i >> 6;
        int t = i & 63;
        float val = qkv[base_off + (size_t)(g * 32 + u) * NP_FULL + (size_t)t * stride_t];
        if (u < 16) sq2[u * 64 + t] = val;
        else        svT[t * 16 + (u - 16)] = val;
    }
    for (int i = tid; i < 4064; i += 256) srel[i] = rel[i];
    __syncthreads();

    // ---- phase 2: diagonal-hoisted q_emb / k_emb ----
    // q_emb[t][j] = sum_c q[c][t] * rel[c][t-j+63]; thread owns diagonal D.
    {
        int D  = tid & 127;          // p = t-j+63 (constant per thread)
        int tg = tid >> 7;           // which half of t
        float rq[8], rk[8];
        #pragma unroll
        for (int c = 0; c < 8; c++) {
            rq[c] = srel[c * 127 + D];
            rk[c] = srel[(8 + c) * 127 + D];
        }
        int dmj = 63 - D;            // j = t + 63 - D
        #pragma unroll
        for (int m = 0; m < 8; m++) {
            int t0 = (tg * 8 + m) * 4;
            float aq0 = 0.f, aq1 = 0.f, aq2 = 0.f, aq3 = 0.f;
            float ak0 = 0.f, ak1 = 0.f, ak2 = 0.f, ak3 = 0.f;
            #pragma unroll
            for (int c = 0; c < 8; c++) {
                float4 q4 = *(const float4*)&sq2[c * 64 + t0];
                float4 k4 = *(const float4*)&sq2[(8 + c) * 64 + t0];
                aq0 += q4.x * rq[c]; aq1 += q4.y * rq[c];
                aq2 += q4.z * rq[c]; aq3 += q4.w * rq[c];
                ak0 += k4.x * rk[c]; ak1 += k4.y * rk[c];
                ak2 += k4.z * rk[c]; ak3 += k4.w * rk[c];
            }
            float aqv[4] = {aq0, aq1, aq2, aq3};
            float akv[4] = {ak0, ak1, ak2, ak3};
            #pragma unroll
            for (int u = 0; u < 4; u++) {
                int t = t0 + u;
                int j = t + dmj;
                if ((unsigned)j < 64u) {
                    sqe[t * 64 + j] = aqv[u];
                    ske[t * 64 + j] = akv[u];
                }
            }
        }
    }
    __syncthreads();

    // ---- BN-sim affine scalars ----
    float sA = bns[g]      * rsqrtf(bns[144 + g]      + EPSV);
    float sB = bns[16 + g] * rsqrtf(bns[144 + 16 + g] + EPSV);
    float sC = bns[32 + g] * rsqrtf(bns[144 + 32 + g] + EPSV);
    float tsum = (bns[48 + g]      - bns[96 + g]      * sA)
               + (bns[48 + 16 + g] - bns[96 + 16 + g] * sB)
               + (bns[48 + 32 + g] - bns[96 + 32 + g] * sC);

    // ---- phase 3: qk[i][j] = sum_t qe[t][i]*ke[t][j]; combine; write ssim ----
    {
        int ti = tid & 15, tj = tid >> 4;
        float acc[4][4];
        #pragma unroll
        for (int u = 0; u < 4; u++)
            #pragma unroll
            for (int v = 0; v < 4; v++) acc[u][v] = 0.f;
        #pragma unroll 4
        for (int t = 0; t < 64; t++) {
            float4 qa = *(const float4*)&sqe[t * 64 + ti * 4];
            float4 kb = *(const float4*)&ske[t * 64 + tj * 4];
            float av[4] = {qa.x, qa.y, qa.z, qa.w};
            float bv[4] = {kb.x, kb.y, kb.z, kb.w};
            #pragma unroll
            for (int u = 0; u < 4; u++)
                #pragma unroll
                for (int v = 0; v < 4; v++) acc[u][v] += av[u] * bv[v];
        }
        #pragma unroll
        for (int u = 0; u < 4; u++) {
            int i = ti * 4 + u;
            float4 qe_i = *(const float4*)&sqe[i * 64 + tj * 4];
            float4 ke_i = *(const float4*)&ske[i * 64 + tj * 4];
            float qv[4] = {qe_i.x, qe_i.y, qe_i.z, qe_i.w};
            float kv[4] = {ke_i.x, ke_i.y, ke_i.z, ke_i.w};
            float4 o4;
            float ov[4];
            #pragma unroll
            for (int v = 0; v < 4; v++)
                ov[v] = sA * acc[u][v] + sB * qv[v] + sC * kv[v] + tsum;
            o4.x = ov[0]; o4.y = ov[1]; o4.z = ov[2]; o4.w = ov[3];
            *(float4*)&ssim[i * 68 + tj * 4] = o4;
        }
    }
    __syncthreads();

    // ---- phase 4: row softmax (4 threads per row) ----
    {
        int r = tid >> 2, l = tid & 3;
        float m = -1e30f;
        #pragma unroll
        for (int jj = 0; jj < 16; jj++) m = fmaxf(m, ssim[r * 68 + l + 4 * jj]);
        m = fmaxf(m, __shfl_xor_sync(0xffffffffu, m, 1));
        m = fmaxf(m, __shfl_xor_sync(0xffffffffu, m, 2));
        float ssum = 0.f;
        #pragma unroll
        for (int jj = 0; jj < 16; jj++) {
            int id = r * 68 + l + 4 * jj;
            float e = __expf(ssim[id] - m);
            ssim[id] = e;
            ssum += e;
        }
        ssum += __shfl_xor_sync(0xffffffffu, ssum, 1);
        ssum += __shfl_xor_sync(0xffffffffu, ssum, 2);
        float inv = 1.f / ssum;
        #pragma unroll
        for (int jj = 0; jj < 16; jj++) ssim[r * 68 + l + 4 * jj] *= inv;
    }
    __syncthreads();

    // ---- phase 5: att / att_e, BN_out, channel-pair sum, write ----
    {
        int i = tid & 63, cb = tid >> 6;   // 4 channels per thread
        int c0 = 16 + cb * 4;              // rel channel base for e-part
        float acca[4] = {0.f, 0.f, 0.f, 0.f};
        float acce[4] = {0.f, 0.f, 0.f, 0.f};
        #pragma unroll 4
        for (int j0 = 0; j0 < 64; j0 += 4) {
            float4 s4 = *(const float4*)&ssim[i * 68 + j0];
            float sarr[4] = {s4.x, s4.y, s4.z, s4.w};
            #pragma unroll
            for (int e = 0; e < 4; e++) {
                int j = j0 + e;
                float s = sarr[e];
                int p = i - j + 63;
                float4 v4 = *(const float4*)&svT[j * 16 + cb * 4];
                float r0 = srel[(c0 + 0) * 127 + p];
                float r1 = srel[(c0 + 1) * 127 + p];
                float r2 = srel[(c0 + 2) * 127 + p];
                float r3 = srel[(c0 + 3) * 127 + p];
                acca[0] += s * v4.x;  acca[1] += s * v4.y;
                acca[2] += s * v4.z;  acca[3] += s * v4.w;
                acce[0] += s * r0;    acce[1] += s * r1;
                acce[2] += s * r2;    acce[3] += s * r3;
            }
        }
        #pragma unroll
        for (int cc = 0; cc < 4; cc++) {
            int c = cb * 4 + cc;
            int chA = g * 32 + 2 * c, chB = chA + 1;
            float sa = bno[chA] * rsqrtf(bno[1536 + chA] + EPSV);
            float ba = bno[512 + chA] - bno[1024 + chA] * sa;
            float sb2 = bno[chB] * rsqrtf(bno[1536 + chB] + EPSV);
            float bb2 = bno[512 + chB] - bno[1024 + chB] * sb2;
            float v = acca[cc] * sa + ba + acce[cc] * sb2 + bb2;
            int ch = g * 16 + c;
            size_t oidx = (dim == 0)
                ? (((size_t)(b * CO + ch) * 64 + i) * 64 + d1)
                : (((size_t)(b * CO + ch) * 64 + d1) * 64 + i);
            out[oidx] = v;
        }
    }
}

// ---------------- 2x2 average pool --------------------------------------
__global__ void pool_kernel(const float* __restrict__ in, float* __restrict__ out, int C)
{
    int idx = blockIdx.x * blockDim.x + threadIdx.x;
    int total = NB * C * NP_HALF;
    if (idx >= total) return;
    int j = idx & 31;
    int i = (idx >> 5) & 31;
    int bc = idx >> 10;
    const float* p = in + (size_t)bc * NP_FULL + (size_t)(2 * i) * 64 + 2 * j;
    out[idx] = 0.25f * (p[0] + p[1] + p[64] + p[65]);
}

// ---------------- final: cbn(conv_out) + conv_res, prelu ----------------
__global__ void final_kernel(const float* __restrict__ Wo,
                             const float* __restrict__ py,
                             const float* __restrict__ Wr,
                             const float* __restrict__ px,
                             float* __restrict__ out,
                             const float* __restrict__ bn,
                             const float* __restrict__ sb,
                             const float* __restrict__ alpha_ptr)
{
    __shared__ float As[16][65];
    __shared__ float Bs[16][64];
    int tid = threadIdx.x;
    int b  = blockIdx.z;
    int o0 = blockIdx.y * 64;
    int p0 = blockIdx.x * 64;
    int ty = tid >> 4, tx = tid & 15;

    float accO[4][4], accR[4][4];
    #pragma unroll
    for (int r = 0; r < 4; r++)
        #pragma unroll
        for (int c = 0; c < 4; c++) { accO[r][c] = 0.f; accR[r][c] = 0.f; }

    const float* Xb = py + (size_t)b * CO * NP_HALF;
    for (int k0 = 0; k0 < CO; k0 += 16) {
        for (int i = tid; i < 1024; i += 256) {
            int oo = i >> 4, kk = i & 15;
            As[kk][oo] = Wo[(size_t)(o0 + oo) * CO + k0 + kk];
        }
        for (int i = tid; i < 1024; i += 256) {
            int kk = i >> 6, pp = i & 63;
            Bs[kk][pp] = Xb[(size_t)(k0 + kk) * NP_HALF + p0 + pp];
        }
        __syncthreads();
        #pragma unroll
        for (int kk = 0; kk < 16; kk++) {
            float a[4], bv[4];
            #pragma unroll
            for (int r = 0; r < 4; r++) a[r] = As[kk][ty + 16 * r];
            #pragma unroll
            for (int c = 0; c < 4; c++) bv[c] = Bs[kk][tx + 16 * c];
            #pragma unroll
            for (int r = 0; r < 4; r++)
                #pragma unroll
                for (int c = 0; c < 4; c++) accO[r][c] += a[r] * bv[c];
        }
        __syncthreads();
    }

    const float* Xr = px + (size_t)b * CINC * NP_HALF;
    for (int k0 = 0; k0 < CINC; k0 += 16) {
        for (int i = tid; i < 1024; i += 256) {
            int oo = i >> 4, kk = i & 15;
            As[kk][oo] = Wr[(size_t)(o0 + oo) * CINC + k0 + kk];
        }
        for (int i = tid; i < 1024; i += 256) {
            int kk = i >> 6, pp = i & 63;
            Bs[kk][pp] = Xr[(size_t)(k0 + kk) * NP_HALF + p0 + pp];
        }
        __syncthreads();
        #pragma unroll
        for (int kk = 0; kk < 16; kk++) {
            float a[4], bv[4];
            #pragma unroll
            for (int r = 0; r < 4; r++) a[r] = As[kk][ty + 16 * r];
            #pragma unroll
            for (int c = 0; c < 4; c++) bv[c] = Bs[kk][tx + 16 * c];
            #pragma unroll
            for (int r = 0; r < 4; r++)
                #pragma unroll
                for (int c = 0; c < 4; c++) accR[r][c] += a[r] * bv[c];
        }
        __syncthreads();
    }

    float alpha = *alpha_ptr;
    #pragma unroll
    for (int r = 0; r < 4; r++) {
        int o = o0 + ty + 16 * r;
        float bsc = bn[o] * rsqrtf(bn[3 * CO + o] + EPSV);
        float bbi = bn[CO + o] - bn[2 * CO + o] * bsc;
        float slat = sb[b * 512 + o];
        float blat = sb[b * 512 + 256 + o];
        #pragma unroll
        for (int c = 0; c < 4; c++) {
            int p = p0 + tx + 16 * c;
            float v = (accO[r][c] * bsc + bbi) * slat + blat + accR[r][c];
            v = v > 0.f ? v : alpha * v;
            out[((size_t)(b * CO + o)) * NP_HALF + p] = v;
        }
    }
}

// ---------------- launcher ----------------------------------------------
extern "C" void kernel_launch(void* const* d_in, const int* in_sizes, int n_in,
                              void* d_out, int out_size)
{
    const float* x         = (const float*)d_in[0];
    const float* latent    = (const float*)d_in[1];
    const float* w_in      = (const float*)d_in[2];
    const float* bn_in     = (const float*)d_in[3];
    const float* lin_in    = (const float*)d_in[4];
    const float* alpha_in  = (const float*)d_in[5];
    const float* a0_wqkv   = (const float*)d_in[6];
    const float* a0_bn_qkv = (const float*)d_in[7];
    const float* a0_bn_sim = (const float*)d_in[8];
    const float* a0_bn_out = (const float*)d_in[9];
    const float* a0_rel    = (const float*)d_in[10];
    const float* a1_wqkv   = (const float*)d_in[11];
    const float* a1_bn_qkv = (const float*)d_in[12];
    const float* a1_bn_sim = (const float*)d_in[13];
    const float* a1_bn_out = (const float*)d_in[14];
    const float* a1_rel    = (const float*)d_in[15];
    const float* w_out     = (const float*)d_in[16];
    const float* bn_out    = (const float*)d_in[17];
    const float* lin_out   = (const float*)d_in[18];
    const float* w_res     = (const float*)d_in[19];
    const float* alpha_fin = (const float*)d_in[20];
    float* out = (float*)d_out;

    float *yb, *qkvb, *pyb, *pxb, *sbb;
    cudaGetSymbolAddress((void**)&yb,   g_y);
    cudaGetSymbolAddress((void**)&qkvb, g_qkv);
    cudaGetSymbolAddress((void**)&pyb,  g_py);
    cudaGetSymbolAddress((void**)&pxb,  g_px);
    cudaGetSymbolAddress((void**)&sbb,  g_sb);

    cudaFuncSetAttribute(attn_kernel, cudaFuncAttributeMaxDynamicSharedMemorySize,
                         ATTN_SMEM_BYTES);

    // 1. latent-conditioned scale/bias
    sb_kernel<<<16, 256>>>(latent, lin_in, lin_out, sbb);

    // 2. y1 = prelu(cbn(conv1x1(w_in, x)))
    {
        dim3 g(NP_FULL / 128, CO / 128, NB);
        conv1x1_kernel<<<g, 256>>>(w_in, x, yb, CINC, CO, NP_FULL,
                                   bn_in, sbb, alpha_in, 0);
    }

    // 3. axial-0
    {
        dim3 g(NP_FULL / 128, (2 * CO) / 128, NB);
        conv1x1_kernel<<<g, 256>>>(a0_wqkv, yb, qkvb, CO, 2 * CO, NP_FULL,
                                   a0_bn_qkv, nullptr, nullptr, 1);
        dim3 ga(256, NG);
        attn_kernel<<<ga, 256, ATTN_SMEM_BYTES>>>(qkvb, yb, a0_rel,
                                                  a0_bn_sim, a0_bn_out, 0);
    }

    // 4. axial-1
    {
        dim3 g(NP_FULL / 128, (2 * CO) / 128, NB);
        conv1x1_kernel<<<g, 256>>>(a1_wqkv, yb, qkvb, CO, 2 * CO, NP_FULL,
                                   a1_bn_qkv, nullptr, nullptr, 1);
        dim3 ga(256, NG);
        attn_kernel<<<ga, 256, ATTN_SMEM_BYTES>>>(qkvb, yb, a1_rel,
                                                  a1_bn_sim, a1_bn_out, 1);
    }

    // 5. pools
    pool_kernel<<<(NB * CO * NP_HALF + 255) / 256, 256>>>(yb, pyb, CO);
    pool_kernel<<<(NB * CINC * NP_HALF + 255) / 256, 256>>>(x, pxb, CINC);

    // 6. final
    {
        dim3 g(NP_HALF / 64, CO / 64, NB);
        final_kernel<<<g, 256>>>(w_out, pyb, w_res, pxb, out,
                                 bn_out, sbb + 2048, alpha_fin);
    }
}

// round 4
// speedup vs baseline: 1.3901x; 1.0359x over previous
#include <cuda_runtime.h>
#include <math.h>

#define EPSV 1e-5f

// Problem dims
#define NB   4
#define CINC 128
#define CO   256
#define LATD 256
#define NG   16
#define NP_FULL 4096     // 64*64
#define NP_HALF 1024     // 32*32

// ---------------- scratch (device globals; no allocation) ----------------
__device__ float g_y[NB * CO * NP_FULL];
__device__ float g_yt[NB * CO * NP_FULL];
__device__ float g_qkv[NB * 2 * CO * NP_FULL];
__device__ float g_py[NB * CO * NP_HALF];
__device__ float g_px[NB * CINC * NP_HALF];
__device__ float g_sb[4096];

// ---------------- latent -> per-(b,ch) scale/bias -----------------------
__global__ void sb_kernel(const float* __restrict__ latent,
                          const float* __restrict__ lin_in,
                          const float* __restrict__ lin_out,
                          float* __restrict__ sb)
{
    int idx = blockIdx.x * blockDim.x + threadIdx.x;
    if (idx >= 4096) return;
    int which = idx >> 11;
    int b = (idx >> 9) & 3;
    int j = idx & 511;
    const float* lin = which ? lin_out : lin_in;
    const float* lt = latent + b * LATD;
    float acc = 0.f;
    #pragma unroll 4
    for (int l = 0; l < LATD; l++) acc += lt[l] * lin[j * LATD + l];
    sb[idx] = acc;
}

// ---------------- 64x64 plane transpose ----------------------------------
__global__ void transpose_kernel(const float* __restrict__ in,
                                 float* __restrict__ out)
{
    __shared__ float tile[32][33];
    int bc = blockIdx.z;
    int x0 = blockIdx.x * 32, y0 = blockIdx.y * 32;
    const float* p = in + (size_t)bc * 4096;
    float* q = out + (size_t)bc * 4096;
    int tx = threadIdx.x, ty = threadIdx.y;    // 32 x 8
    #pragma unroll
    for (int r = 0; r < 32; r += 8)
        tile[ty + r][tx] = p[(size_t)(y0 + ty + r) * 64 + x0 + tx];
    __syncthreads();
    #pragma unroll
    for (int r = 0; r < 32; r += 8)
        q[(size_t)(x0 + ty + r) * 64 + y0 + tx] = tile[tx][ty + r];
}

// ---------------- SGEMM 1x1 conv: 128x128 tile, 8x8 per thread ----------
// mode 0: y = prelu(cbn(conv));  mode 1: y = bn(conv)
__global__ __launch_bounds__(256)
void conv1x1_kernel(const float* __restrict__ Wm,   // (Cout, Cin)
                    const float* __restrict__ X,    // (B, Cin, NP)
                    float* __restrict__ Y,          // (B, Cout, NP)
                    int Cin, int Cout, int NP,
                    const float* __restrict__ bn,
                    const float* __restrict__ sb,
                    const float* __restrict__ alpha_ptr,
                    int mode)
{
    __shared__ float As[8][128];
    __shared__ float Bs[8][128];
    int tid = threadIdx.x;
    int b  = blockIdx.z;
    int o0 = blockIdx.y * 128;
    int p0 = blockIdx.x * 128;
    const float* Xb = X + (size_t)b * Cin * NP;

    int arow = tid >> 1, akq = (tid & 1) * 4;
    int brow = tid >> 5, bcol = (tid & 31) * 4;
    int tx = tid & 15, ty = tid >> 4;

    float4 pa = *(const float4*)&Wm[(size_t)(o0 + arow) * Cin + akq];
    float4 pb = *(const float4*)&Xb[(size_t)brow * NP + p0 + bcol];

    float acc[8][8];
    #pragma unroll
    for (int r = 0; r < 8; r++)
        #pragma unroll
        for (int c = 0; c < 8; c++) acc[r][c] = 0.f;

    int nk = Cin >> 3;
    for (int kc = 0; kc < nk; kc++) {
        As[akq + 0][arow] = pa.x;
        As[akq + 1][arow] = pa.y;
        As[akq + 2][arow] = pa.z;
        As[akq + 3][arow] = pa.w;
        *(float4*)&Bs[brow][bcol] = pb;
        __syncthreads();
        if (kc + 1 < nk) {
            int k0 = (kc + 1) << 3;
            pa = *(const float4*)&Wm[(size_t)(o0 + arow) * Cin + k0 + akq];
            pb = *(const float4*)&Xb[(size_t)(k0 + brow) * NP + p0 + bcol];
        }
        #pragma unroll
        for (int kk = 0; kk < 8; kk++) {
            float4 a0 = *(const float4*)&As[kk][ty * 4];
            float4 a1 = *(const float4*)&As[kk][ty * 4 + 64];
            float4 b0 = *(const float4*)&Bs[kk][tx * 4];
            float4 b1 = *(const float4*)&Bs[kk][tx * 4 + 64];
            float av[8] = {a0.x, a0.y, a0.z, a0.w, a1.x, a1.y, a1.z, a1.w};
            float bv[8] = {b0.x, b0.y, b0.z, b0.w, b1.x, b1.y, b1.z, b1.w};
            #pragma unroll
            for (int r = 0; r < 8; r++)
                #pragma unroll
                for (int c = 0; c < 8; c++)
                    acc[r][c] += av[r] * bv[c];
        }
        __syncthreads();
    }

    float alpha = (mode == 0) ? *alpha_ptr : 0.f;
    #pragma unroll
    for (int r = 0; r < 8; r++) {
        int m = (r < 4) ? (ty * 4 + r) : (64 + ty * 4 + r - 4);
        int o = o0 + m;
        float bsc = bn[o] * rsqrtf(bn[3 * Cout + o] + EPSV);
        float bbi = bn[Cout + o] - bn[2 * Cout + o] * bsc;
        float slat = 1.f, blat = 0.f;
        if (mode == 0) {
            slat = sb[b * 2 * Cout + o];
            blat = sb[b * 2 * Cout + Cout + o];
        }
        #pragma unroll
        for (int cq = 0; cq < 2; cq++) {
            float4 v;
            float vv[4];
            #pragma unroll
            for (int cc = 0; cc < 4; cc++) {
                float val = acc[r][cq * 4 + cc] * bsc + bbi;
                if (mode == 0) {
                    val = val * slat + blat;
                    val = val > 0.f ? val : alpha * val;
                }
                vv[cc] = val;
            }
            v.x = vv[0]; v.y = vv[1]; v.z = vv[2]; v.w = vv[3];
            int p = p0 + tx * 4 + cq * 64;
            *(float4*)&Y[((size_t)(b * Cout + o)) * NP + p] = v;
        }
    }
}

// ---------------- fused axial attention core (512 threads) ---------------
// Input qkv is stored with the ATTEND axis contiguous: qkv[b][ch][d1][t].
// Output written as out[b][ch][d1*64 + i] (i contiguous).
// smem layout (floats):
//   sq2  : [16][64]  (q c=0..7 rows, k c=8..15 rows; t contiguous)   1024
//   svT  : [64][16]                                                  1024
//   srel : [32][127] row-major (scalar coalesced reads)              4064
//   sqe  : [64][64]                                                  4096
//   ske  : [64][64]                                                  4096
//   ssim : [64][68]                                                  4352
#define OFF_SQ2  0
#define OFF_SV   1024
#define OFF_REL  2048
#define OFF_QE   6112
#define OFF_KE   10208
#define OFF_SIM  14304
#define ATTN_SMEM_FLOATS 18656
#define ATTN_SMEM_BYTES (ATTN_SMEM_FLOATS * 4)

__global__ __launch_bounds__(512)
void attn_kernel(const float* __restrict__ qkv,   // (B,512,64,64) t-contig
                 float* __restrict__ out,          // (B,256,64,64) i-contig
                 const float* __restrict__ rel,    // (32,127)
                 const float* __restrict__ bns,    // (4,48)
                 const float* __restrict__ bno)    // (4,512)
{
    extern __shared__ float sm[];
    float* sq2  = sm + OFF_SQ2;
    float* svT  = sm + OFF_SV;
    float* srel = sm + OFF_REL;
    float* sqe  = sm + OFF_QE;
    float* ske  = sm + OFF_KE;
    float* ssim = sm + OFF_SIM;

    int tid = threadIdx.x;
    int bn = blockIdx.x;
    int g  = blockIdx.y;
    int b  = bn >> 6, d1 = bn & 63;
    size_t base_off = (size_t)b * 512 * NP_FULL + (size_t)d1 * 64;

    // ---- phase 1: load q/k in [c][t], v in [t][c], rel row-major ----
    #pragma unroll
    for (int i = tid; i < 2048; i += 512) {
        int u = i >> 6;
        int t = i & 63;
        float val = qkv[base_off + (size_t)(g * 32 + u) * NP_FULL + t];
        if (u < 16) sq2[u * 64 + t] = val;
        else        svT[t * 16 + (u - 16)] = val;
    }
    for (int i = tid; i < 4064; i += 512) srel[i] = rel[i];
    __syncthreads();

    // ---- phase 2: diagonal-hoisted q_emb / k_emb ----
    // thread owns diagonal D (= t-j+63) and a 16-wide t chunk
    {
        int D  = tid & 127;
        int tg = tid >> 7;            // 0..3 -> t chunk of 16
        float rq[8], rk[8];
        #pragma unroll
        for (int c = 0; c < 8; c++) {
            rq[c] = srel[c * 127 + D];
            rk[c] = srel[(8 + c) * 127 + D];
        }
        int dmj = 63 - D;             // j = t + 63 - D
        #pragma unroll
        for (int m = 0; m < 4; m++) {
            int t0 = tg * 16 + m * 4;
            float aq0 = 0.f, aq1 = 0.f, aq2 = 0.f, aq3 = 0.f;
            float ak0 = 0.f, ak1 = 0.f, ak2 = 0.f, ak3 = 0.f;
            #pragma unroll
            for (int c = 0; c < 8; c++) {
                float4 q4 = *(const float4*)&sq2[c * 64 + t0];
                float4 k4 = *(const float4*)&sq2[(8 + c) * 64 + t0];
                aq0 += q4.x * rq[c]; aq1 += q4.y * rq[c];
                aq2 += q4.z * rq[c]; aq3 += q4.w * rq[c];
                ak0 += k4.x * rk[c]; ak1 += k4.y * rk[c];
                ak2 += k4.z * rk[c]; ak3 += k4.w * rk[c];
            }
            float aqv[4] = {aq0, aq1, aq2, aq3};
            float akv[4] = {ak0, ak1, ak2, ak3};
            #pragma unroll
            for (int u = 0; u < 4; u++) {
                int t = t0 + u;
                int j = t + dmj;
                if ((unsigned)j < 64u) {
                    sqe[t * 64 + j] = aqv[u];
                    ske[t * 64 + j] = akv[u];
                }
            }
        }
    }
    __syncthreads();

    // ---- BN-sim affine scalars ----
    float sA = bns[g]      * rsqrtf(bns[144 + g]      + EPSV);
    float sB = bns[16 + g] * rsqrtf(bns[144 + 16 + g] + EPSV);
    float sC = bns[32 + g] * rsqrtf(bns[144 + 32 + g] + EPSV);
    float tsum = (bns[48 + g]      - bns[96 + g]      * sA)
               + (bns[48 + 16 + g] - bns[96 + 16 + g] * sB)
               + (bns[48 + 32 + g] - bns[96 + 32 + g] * sC);

    // ---- phase 3: qk[i][j] = sum_t qe[t][i]*ke[t][j]; 2x4 per thread ----
    {
        int tj = tid & 15, ti = tid >> 4;   // ti 0..31: i pair; tj: j quad
        float acc[2][4];
        #pragma unroll
        for (int u = 0; u < 2; u++)
            #pragma unroll
            for (int v = 0; v < 4; v++) acc[u][v] = 0.f;
        #pragma unroll 4
        for (int t = 0; t < 64; t++) {
            float2 qa = *(const float2*)&sqe[t * 64 + ti * 2];
            float4 kb = *(const float4*)&ske[t * 64 + tj * 4];
            float av[2] = {qa.x, qa.y};
            float bv[4] = {kb.x, kb.y, kb.z, kb.w};
            #pragma unroll
            for (int u = 0; u < 2; u++)
                #pragma unroll
                for (int v = 0; v < 4; v++) acc[u][v] += av[u] * bv[v];
        }
        #pragma unroll
        for (int u = 0; u < 2; u++) {
            int i = ti * 2 + u;
            float4 qe_i = *(const float4*)&sqe[i * 64 + tj * 4];
            float4 ke_i = *(const float4*)&ske[i * 64 + tj * 4];
            float qv[4] = {qe_i.x, qe_i.y, qe_i.z, qe_i.w};
            float kv[4] = {ke_i.x, ke_i.y, ke_i.z, ke_i.w};
            float4 o4;
            float ov[4];
            #pragma unroll
            for (int v = 0; v < 4; v++)
                ov[v] = sA * acc[u][v] + sB * qv[v] + sC * kv[v] + tsum;
            o4.x = ov[0]; o4.y = ov[1]; o4.z = ov[2]; o4.w = ov[3];
            *(float4*)&ssim[i * 68 + tj * 4] = o4;
        }
    }
    __syncthreads();

    // ---- phase 4: row softmax (8 threads per row) ----
    {
        int r = tid >> 3, l = tid & 7;
        float m = -1e30f;
        #pragma unroll
        for (int jj = 0; jj < 8; jj++) m = fmaxf(m, ssim[r * 68 + l + 8 * jj]);
        m = fmaxf(m, __shfl_xor_sync(0xffffffffu, m, 1));
        m = fmaxf(m, __shfl_xor_sync(0xffffffffu, m, 2));
        m = fmaxf(m, __shfl_xor_sync(0xffffffffu, m, 4));
        float ssum = 0.f;
        #pragma unroll
        for (int jj = 0; jj < 8; jj++) {
            int id = r * 68 + l + 8 * jj;
            float e = __expf(ssim[id] - m);
            ssim[id] = e;
            ssum += e;
        }
        ssum += __shfl_xor_sync(0xffffffffu, ssum, 1);
        ssum += __shfl_xor_sync(0xffffffffu, ssum, 2);
        ssum += __shfl_xor_sync(0xffffffffu, ssum, 4);
        float inv = 1.f / ssum;
        #pragma unroll
        for (int jj = 0; jj < 8; jj++) ssim[r * 68 + l + 8 * jj] *= inv;
    }
    __syncthreads();

    // ---- phase 5: att / att_e, BN_out, channel-pair sum, write ----
    {
        int i = tid & 63, cb = tid >> 6;   // cb 0..7: 2 channels per thread
        int c0 = 16 + cb * 2;              // rel channel base for e-part
        float acca0 = 0.f, acca1 = 0.f, acce0 = 0.f, acce1 = 0.f;
        #pragma unroll 4
        for (int j0 = 0; j0 < 64; j0 += 4) {
            float4 s4 = *(const float4*)&ssim[i * 68 + j0];
            float sarr[4] = {s4.x, s4.y, s4.z, s4.w};
            #pragma unroll
            for (int e = 0; e < 4; e++) {
                int j = j0 + e;
                float s = sarr[e];
                int p = i - j + 63;
                float2 v2 = *(const float2*)&svT[j * 16 + cb * 2];
                float r0 = srel[(c0 + 0) * 127 + p];
                float r1 = srel[(c0 + 1) * 127 + p];
                acca0 += s * v2.x;  acca1 += s * v2.y;
                acce0 += s * r0;    acce1 += s * r1;
            }
        }
        float accav[2] = {acca0, acca1};
        float accev[2] = {acce0, acce1};
        #pragma unroll
        for (int cc = 0; cc < 2; cc++) {
            int c = cb * 2 + cc;
            int chA = g * 32 + 2 * c, chB = chA + 1;
            float sa = bno[chA] * rsqrtf(bno[1536 + chA] + EPSV);
            float ba = bno[512 + chA] - bno[1024 + chA] * sa;
            float sb2 = bno[chB] * rsqrtf(bno[1536 + chB] + EPSV);
            float bb2 = bno[512 + chB] - bno[1024 + chB] * sb2;
            float v = accav[cc] * sa + ba + accev[cc] * sb2 + bb2;
            int ch = g * 16 + c;
            out[((size_t)(b * CO + ch)) * NP_FULL + d1 * 64 + i] = v;
        }
    }
}

// ---------------- 2x2 average pool --------------------------------------
__global__ void pool_kernel(const float* __restrict__ in, float* __restrict__ out, int C)
{
    int idx = blockIdx.x * blockDim.x + threadIdx.x;
    int total = NB * C * NP_HALF;
    if (idx >= total) return;
    int j = idx & 31;
    int i = (idx >> 5) & 31;
    int bc = idx >> 10;
    const float* p = in + (size_t)bc * NP_FULL + (size_t)(2 * i) * 64 + 2 * j;
    out[idx] = 0.25f * (p[0] + p[1] + p[64] + p[65]);
}

// ---------------- final: cbn(conv_out) + conv_res, prelu ----------------
__global__ void final_kernel(const float* __restrict__ Wo,
                             const float* __restrict__ py,
                             const float* __restrict__ Wr,
                             const float* __restrict__ px,
                             float* __restrict__ out,
                             const float* __restrict__ bn,
                             const float* __restrict__ sb,
                             const float* __restrict__ alpha_ptr)
{
    __shared__ float As[16][65];
    __shared__ float Bs[16][64];
    int tid = threadIdx.x;
    int b  = blockIdx.z;
    int o0 = blockIdx.y * 64;
    int p0 = blockIdx.x * 64;
    int ty = tid >> 4, tx = tid & 15;

    float accO[4][4], accR[4][4];
    #pragma unroll
    for (int r = 0; r < 4; r++)
        #pragma unroll
        for (int c = 0; c < 4; c++) { accO[r][c] = 0.f; accR[r][c] = 0.f; }

    const float* Xb = py + (size_t)b * CO * NP_HALF;
    for (int k0 = 0; k0 < CO; k0 += 16) {
        for (int i = tid; i < 1024; i += 256) {
            int oo = i >> 4, kk = i & 15;
            As[kk][oo] = Wo[(size_t)(o0 + oo) * CO + k0 + kk];
        }
        for (int i = tid; i < 1024; i += 256) {
            int kk = i >> 6, pp = i & 63;
            Bs[kk][pp] = Xb[(size_t)(k0 + kk) * NP_HALF + p0 + pp];
        }
        __syncthreads();
        #pragma unroll
        for (int kk = 0; kk < 16; kk++) {
            float a[4], bv[4];
            #pragma unroll
            for (int r = 0; r < 4; r++) a[r] = As[kk][ty + 16 * r];
            #pragma unroll
            for (int c = 0; c < 4; c++) bv[c] = Bs[kk][tx + 16 * c];
            #pragma unroll
            for (int r = 0; r < 4; r++)
                #pragma unroll
                for (int c = 0; c < 4; c++) accO[r][c] += a[r] * bv[c];
        }
        __syncthreads();
    }

    const float* Xr = px + (size_t)b * CINC * NP_HALF;
    for (int k0 = 0; k0 < CINC; k0 += 16) {
        for (int i = tid; i < 1024; i += 256) {
            int oo = i >> 4, kk = i & 15;
            As[kk][oo] = Wr[(size_t)(o0 + oo) * CINC + k0 + kk];
        }
        for (int i = tid; i < 1024; i += 256) {
            int kk = i >> 6, pp = i & 63;
            Bs[kk][pp] = Xr[(size_t)(k0 + kk) * NP_HALF + p0 + pp];
        }
        __syncthreads();
        #pragma unroll
        for (int kk = 0; kk < 16; kk++) {
            float a[4], bv[4];
            #pragma unroll
            for (int r = 0; r < 4; r++) a[r] = As[kk][ty + 16 * r];
            #pragma unroll
            for (int c = 0; c < 4; c++) bv[c] = Bs[kk][tx + 16 * c];
            #pragma unroll
            for (int r = 0; r < 4; r++)
                #pragma unroll
                for (int c = 0; c < 4; c++) accR[r][c] += a[r] * bv[c];
        }
        __syncthreads();
    }

    float alpha = *alpha_ptr;
    #pragma unroll
    for (int r = 0; r < 4; r++) {
        int o = o0 + ty + 16 * r;
        float bsc = bn[o] * rsqrtf(bn[3 * CO + o] + EPSV);
        float bbi = bn[CO + o] - bn[2 * CO + o] * bsc;
        float slat = sb[b * 512 + o];
        float blat = sb[b * 512 + 256 + o];
        #pragma unroll
        for (int c = 0; c < 4; c++) {
            int p = p0 + tx + 16 * c;
            float v = (accO[r][c] * bsc + bbi) * slat + blat + accR[r][c];
            v = v > 0.f ? v : alpha * v;
            out[((size_t)(b * CO + o)) * NP_HALF + p] = v;
        }
    }
}

// ---------------- launcher ----------------------------------------------
extern "C" void kernel_launch(void* const* d_in, const int* in_sizes, int n_in,
                              void* d_out, int out_size)
{
    const float* x         = (const float*)d_in[0];
    const float* latent    = (const float*)d_in[1];
    const float* w_in      = (const float*)d_in[2];
    const float* bn_in     = (const float*)d_in[3];
    const float* lin_in    = (const float*)d_in[4];
    const float* alpha_in  = (const float*)d_in[5];
    const float* a0_wqkv   = (const float*)d_in[6];
    const float* a0_bn_qkv = (const float*)d_in[7];
    const float* a0_bn_sim = (const float*)d_in[8];
    const float* a0_bn_out = (const float*)d_in[9];
    const float* a0_rel    = (const float*)d_in[10];
    const float* a1_wqkv   = (const float*)d_in[11];
    const float* a1_bn_qkv = (const float*)d_in[12];
    const float* a1_bn_sim = (const float*)d_in[13];
    const float* a1_bn_out = (const float*)d_in[14];
    const float* a1_rel    = (const float*)d_in[15];
    const float* w_out     = (const float*)d_in[16];
    const float* bn_out    = (const float*)d_in[17];
    const float* lin_out   = (const float*)d_in[18];
    const float* w_res     = (const float*)d_in[19];
    const float* alpha_fin = (const float*)d_in[20];
    float* out = (float*)d_out;

    float *yb, *ytb, *qkvb, *pyb, *pxb, *sbb;
    cudaGetSymbolAddress((void**)&yb,   g_y);
    cudaGetSymbolAddress((void**)&ytb,  g_yt);
    cudaGetSymbolAddress((void**)&qkvb, g_qkv);
    cudaGetSymbolAddress((void**)&pyb,  g_py);
    cudaGetSymbolAddress((void**)&pxb,  g_px);
    cudaGetSymbolAddress((void**)&sbb,  g_sb);

    cudaFuncSetAttribute(attn_kernel, cudaFuncAttributeMaxDynamicSharedMemorySize,
                         ATTN_SMEM_BYTES);

    dim3 tgrid(2, 2, NB * CO);
    dim3 tblk(32, 8);

    // 1. latent-conditioned scale/bias
    sb_kernel<<<16, 256>>>(latent, lin_in, lin_out, sbb);

    // 2. y = prelu(cbn(conv1x1(w_in, x)))   layout [h][w]
    {
        dim3 g(NP_FULL / 128, CO / 128, NB);
        conv1x1_kernel<<<g, 256>>>(w_in, x, yb, CINC, CO, NP_FULL,
                                   bn_in, sbb, alpha_in, 0);
    }

    // 3. transpose y -> yt ([w][h]); qkv conv a0 on yt; attn0 (over h, t contig)
    transpose_kernel<<<tgrid, tblk>>>(yb, ytb);
    {
        dim3 g(NP_FULL / 128, (2 * CO) / 128, NB);
        conv1x1_kernel<<<g, 256>>>(a0_wqkv, ytb, qkvb, CO, 2 * CO, NP_FULL,
                                   a0_bn_qkv, nullptr, nullptr, 1);
        dim3 ga(256, NG);
        attn_kernel<<<ga, 512, ATTN_SMEM_BYTES>>>(qkvb, yb, a0_rel,
                                                  a0_bn_sim, a0_bn_out);
        // y now holds [w][h] order
    }

    // 4. transpose y -> yt ([h][w]); qkv conv a1 on yt; attn1 (over w, t contig)
    transpose_kernel<<<tgrid, tblk>>>(yb, ytb);
    {
        dim3 g(NP_FULL / 128, (2 * CO) / 128, NB);
        conv1x1_kernel<<<g, 256>>>(a1_wqkv, ytb, qkvb, CO, 2 * CO, NP_FULL,
                                   a1_bn_qkv, nullptr, nullptr, 1);
        dim3 ga(256, NG);
        attn_kernel<<<ga, 512, ATTN_SMEM_BYTES>>>(qkvb, yb, a1_rel,
                                                  a1_bn_sim, a1_bn_out);
        // y now holds normal [h][w] order
    }

    // 5. pools
    pool_kernel<<<(NB * CO * NP_HALF + 255) / 256, 256>>>(yb, pyb, CO);
    pool_kernel<<<(NB * CINC * NP_HALF + 255) / 256, 256>>>(x, pxb, CINC);

    // 6. final
    {
        dim3 g(NP_HALF / 64, CO / 64, NB);
        final_kernel<<<g, 256>>>(w_out, pyb, w_res, pxb, out,
                                 bn_out, sbb + 2048, alpha_fin);
    }
}

// round 5
// speedup vs baseline: 1.4378x; 1.0343x over previous
#include <cuda_runtime.h>
#include <math.h>
#include <stdint.h>

#define EPSV 1e-5f

// Problem dims
#define NB   4
#define CINC 128
#define CO   256
#define LATD 256
#define NG   16
#define NP_FULL 4096     // 64*64
#define NP_HALF 1024     // 32*32

// ---------------- scratch (device globals; no allocation) ----------------
__device__ float g_y[NB * CO * NP_FULL];
__device__ float g_yt[NB * CO * NP_FULL];
__device__ float g_qkv[NB * 2 * CO * NP_FULL];
__device__ float g_py[NB * CO * NP_HALF];
__device__ float g_px[NB * CINC * NP_HALF];
__device__ float g_sb[4096];

// ---------------- latent -> per-(b,ch) scale/bias -----------------------
__global__ void sb_kernel(const float* __restrict__ latent,
                          const float* __restrict__ lin_in,
                          const float* __restrict__ lin_out,
                          float* __restrict__ sb)
{
    int idx = blockIdx.x * blockDim.x + threadIdx.x;
    if (idx >= 4096) return;
    int which = idx >> 11;
    int b = (idx >> 9) & 3;
    int j = idx & 511;
    const float* lin = which ? lin_out : lin_in;
    const float* lt = latent + b * LATD;
    float acc = 0.f;
    #pragma unroll 4
    for (int l = 0; l < LATD; l++) acc += lt[l] * lin[j * LATD + l];
    sb[idx] = acc;
}

// ---------------- 64x64 plane transpose ----------------------------------
__global__ void transpose_kernel(const float* __restrict__ in,
                                 float* __restrict__ out)
{
    __shared__ float tile[32][33];
    int bc = blockIdx.z;
    int x0 = blockIdx.x * 32, y0 = blockIdx.y * 32;
    const float* p = in + (size_t)bc * 4096;
    float* q = out + (size_t)bc * 4096;
    int tx = threadIdx.x, ty = threadIdx.y;    // 32 x 8
    #pragma unroll
    for (int r = 0; r < 32; r += 8)
        tile[ty + r][tx] = p[(size_t)(y0 + ty + r) * 64 + x0 + tx];
    __syncthreads();
    #pragma unroll
    for (int r = 0; r < 32; r += 8)
        q[(size_t)(x0 + ty + r) * 64 + y0 + tx] = tile[tx][ty + r];
}

// ---------------- TF32 helpers -------------------------------------------
__device__ __forceinline__ void cvt_tf32_pair(float v, uint32_t& hi, uint32_t& lo)
{
    asm("cvt.rna.tf32.f32 %0, %1;" : "=r"(hi) : "f"(v));
    float hf = __uint_as_float(hi);
    float r = v - hf;
    asm("cvt.rna.tf32.f32 %0, %1;" : "=r"(lo) : "f"(r));
}

__device__ __forceinline__ void mma_tf32(float* c, const uint32_t* a,
                                         uint32_t b0, uint32_t b1)
{
    asm volatile(
        "mma.sync.aligned.m16n8k8.row.col.f32.tf32.tf32.f32 "
        "{%0,%1,%2,%3}, {%4,%5,%6,%7}, {%8,%9}, {%0,%1,%2,%3};"
        : "+f"(c[0]), "+f"(c[1]), "+f"(c[2]), "+f"(c[3])
        : "r"(a[0]), "r"(a[1]), "r"(a[2]), "r"(a[3]), "r"(b0), "r"(b1));
}

// ---------------- tensor-core 1x1 conv (3xTF32) ---------------------------
// C[Cout][NP] = W[Cout][Cin] @ X[Cin][NP], tile 128x128, BK=16.
// 8 warps: warp grid 2(m) x 4(n); warp tile 64x32; frags 4m x 4n.
// mode 0: y = prelu(cbn(conv));  mode 1: y = bn(conv)
__global__ __launch_bounds__(256)
void conv1x1_tc_kernel(const float* __restrict__ Wm,
                       const float* __restrict__ X,
                       float* __restrict__ Y,
                       int Cin, int Cout, int NP,
                       const float* __restrict__ bn,
                       const float* __restrict__ sb,
                       const float* __restrict__ alpha_ptr,
                       int mode)
{
    __shared__ float As[16][136];   // [k][m]  (W transposed)
    __shared__ float Bs[16][136];   // [k][n]
    int tid = threadIdx.x;
    int b  = blockIdx.z;
    int o0 = blockIdx.y * 128;
    int p0 = blockIdx.x * 128;
    const float* Xb = X + (size_t)b * Cin * NP;

    int lane = tid & 31, warp = tid >> 5;
    int warp_m = warp & 1, warp_n = warp >> 1;   // 2 x 4
    int gid = lane >> 2, tig = lane & 3;

    // loader mappings
    int arow = tid >> 1;            // m 0..127
    int akq  = (tid & 1) * 8;       // k offset 0/8
    int bkr  = tid >> 4;            // k 0..15
    int bn8  = (tid & 15) * 8;      // n offset

    float4 pa0 = *(const float4*)&Wm[(size_t)(o0 + arow) * Cin + akq];
    float4 pa1 = *(const float4*)&Wm[(size_t)(o0 + arow) * Cin + akq + 4];
    float4 pb0 = *(const float4*)&Xb[(size_t)bkr * NP + p0 + bn8];
    float4 pb1 = *(const float4*)&Xb[(size_t)bkr * NP + p0 + bn8 + 4];

    float c[4][4][4];
    #pragma unroll
    for (int fm = 0; fm < 4; fm++)
        #pragma unroll
        for (int fn = 0; fn < 4; fn++)
            #pragma unroll
            for (int e = 0; e < 4; e++) c[fm][fn][e] = 0.f;

    int nk = Cin >> 4;
    for (int kc = 0; kc < nk; kc++) {
        As[akq + 0][arow] = pa0.x;
        As[akq + 1][arow] = pa0.y;
        As[akq + 2][arow] = pa0.z;
        As[akq + 3][arow] = pa0.w;
        As[akq + 4][arow] = pa1.x;
        As[akq + 5][arow] = pa1.y;
        As[akq + 6][arow] = pa1.z;
        As[akq + 7][arow] = pa1.w;
        *(float4*)&Bs[bkr][bn8] = pb0;
        *(float4*)&Bs[bkr][bn8 + 4] = pb1;
        __syncthreads();
        if (kc + 1 < nk) {
            int k0 = (kc + 1) << 4;
            pa0 = *(const float4*)&Wm[(size_t)(o0 + arow) * Cin + k0 + akq];
            pa1 = *(const float4*)&Wm[(size_t)(o0 + arow) * Cin + k0 + akq + 4];
            pb0 = *(const float4*)&Xb[(size_t)(k0 + bkr) * NP + p0 + bn8];
            pb1 = *(const float4*)&Xb[(size_t)(k0 + bkr) * NP + p0 + bn8 + 4];
        }
        #pragma unroll
        for (int ks = 0; ks < 2; ks++) {
            int kb = ks * 8;
            // B frags for all fn (hi/lo)
            uint32_t bh[4][2], bl[4][2];
            #pragma unroll
            for (int fn = 0; fn < 4; fn++) {
                int n = warp_n * 32 + fn * 8 + gid;
                float w0 = Bs[kb + tig][n];
                float w1 = Bs[kb + tig + 4][n];
                cvt_tf32_pair(w0, bh[fn][0], bl[fn][0]);
                cvt_tf32_pair(w1, bh[fn][1], bl[fn][1]);
            }
            #pragma unroll
            for (int fm = 0; fm < 4; fm++) {
                int m = warp_m * 64 + fm * 16 + gid;
                float v0 = As[kb + tig][m];
                float v1 = As[kb + tig][m + 8];
                float v2 = As[kb + tig + 4][m];
                float v3 = As[kb + tig + 4][m + 8];
                uint32_t ah[4], al[4];
                cvt_tf32_pair(v0, ah[0], al[0]);
                cvt_tf32_pair(v1, ah[1], al[1]);
                cvt_tf32_pair(v2, ah[2], al[2]);
                cvt_tf32_pair(v3, ah[3], al[3]);
                #pragma unroll
                for (int fn = 0; fn < 4; fn++) {
                    mma_tf32(c[fm][fn], ah, bh[fn][0], bh[fn][1]);
                    mma_tf32(c[fm][fn], ah, bl[fn][0], bl[fn][1]);
                    mma_tf32(c[fm][fn], al, bh[fn][0], bh[fn][1]);
                }
            }
        }
        __syncthreads();
    }

    // ---- epilogue: BN (+ latent cbn + prelu), write float2 pairs ----
    float alpha = (mode == 0) ? *alpha_ptr : 0.f;
    #pragma unroll
    for (int fm = 0; fm < 4; fm++) {
        int o_t = o0 + warp_m * 64 + fm * 16 + gid;
        int o_b = o_t + 8;
        float bsc_t = bn[o_t] * rsqrtf(bn[3 * Cout + o_t] + EPSV);
        float bbi_t = bn[Cout + o_t] - bn[2 * Cout + o_t] * bsc_t;
        float bsc_b = bn[o_b] * rsqrtf(bn[3 * Cout + o_b] + EPSV);
        float bbi_b = bn[Cout + o_b] - bn[2 * Cout + o_b] * bsc_b;
        float sl_t = 1.f, bl_t = 0.f, sl_b = 1.f, bl_b = 0.f;
        if (mode == 0) {
            sl_t = sb[b * 2 * Cout + o_t];
            bl_t = sb[b * 2 * Cout + Cout + o_t];
            sl_b = sb[b * 2 * Cout + o_b];
            bl_b = sb[b * 2 * Cout + Cout + o_b];
        }
        #pragma unroll
        for (int fn = 0; fn < 4; fn++) {
            int p = p0 + warp_n * 32 + fn * 8 + 2 * tig;
            float v0 = c[fm][fn][0] * bsc_t + bbi_t;
            float v1 = c[fm][fn][1] * bsc_t + bbi_t;
            float v2 = c[fm][fn][2] * bsc_b + bbi_b;
            float v3 = c[fm][fn][3] * bsc_b + bbi_b;
            if (mode == 0) {
                v0 = v0 * sl_t + bl_t; v0 = v0 > 0.f ? v0 : alpha * v0;
                v1 = v1 * sl_t + bl_t; v1 = v1 > 0.f ? v1 : alpha * v1;
                v2 = v2 * sl_b + bl_b; v2 = v2 > 0.f ? v2 : alpha * v2;
                v3 = v3 * sl_b + bl_b; v3 = v3 > 0.f ? v3 : alpha * v3;
            }
            float2 top; top.x = v0; top.y = v1;
            float2 bot; bot.x = v2; bot.y = v3;
            *(float2*)&Y[((size_t)(b * Cout + o_t)) * NP + p] = top;
            *(float2*)&Y[((size_t)(b * Cout + o_b)) * NP + p] = bot;
        }
    }
}

// ---------------- fused axial attention core (512 threads) ---------------
#define OFF_SQ2  0
#define OFF_SV   1024
#define OFF_REL  2048
#define OFF_QE   6112
#define OFF_KE   10208
#define OFF_SIM  14304
#define ATTN_SMEM_FLOATS 18656
#define ATTN_SMEM_BYTES (ATTN_SMEM_FLOATS * 4)

__global__ __launch_bounds__(512)
void attn_kernel(const float* __restrict__ qkv,   // (B,512,64,64) t-contig
                 float* __restrict__ out,          // (B,256,64,64) i-contig
                 const float* __restrict__ rel,    // (32,127)
                 const float* __restrict__ bns,    // (4,48)
                 const float* __restrict__ bno)    // (4,512)
{
    extern __shared__ float sm[];
    float* sq2  = sm + OFF_SQ2;
    float* svT  = sm + OFF_SV;
    float* srel = sm + OFF_REL;
    float* sqe  = sm + OFF_QE;
    float* ske  = sm + OFF_KE;
    float* ssim = sm + OFF_SIM;

    int tid = threadIdx.x;
    int bn = blockIdx.x;
    int g  = blockIdx.y;
    int b  = bn >> 6, d1 = bn & 63;
    size_t base_off = (size_t)b * 512 * NP_FULL + (size_t)d1 * 64;

    #pragma unroll
    for (int i = tid; i < 2048; i += 512) {
        int u = i >> 6;
        int t = i & 63;
        float val = qkv[base_off + (size_t)(g * 32 + u) * NP_FULL + t];
        if (u < 16) sq2[u * 64 + t] = val;
        else        svT[t * 16 + (u - 16)] = val;
    }
    for (int i = tid; i < 4064; i += 512) srel[i] = rel[i];
    __syncthreads();

    {
        int D  = tid & 127;
        int tg = tid >> 7;
        float rq[8], rk[8];
        #pragma unroll
        for (int c = 0; c < 8; c++) {
            rq[c] = srel[c * 127 + D];
            rk[c] = srel[(8 + c) * 127 + D];
        }
        int dmj = 63 - D;
        #pragma unroll
        for (int m = 0; m < 4; m++) {
            int t0 = tg * 16 + m * 4;
            float aq0 = 0.f, aq1 = 0.f, aq2 = 0.f, aq3 = 0.f;
            float ak0 = 0.f, ak1 = 0.f, ak2 = 0.f, ak3 = 0.f;
            #pragma unroll
            for (int c = 0; c < 8; c++) {
                float4 q4 = *(const float4*)&sq2[c * 64 + t0];
                float4 k4 = *(const float4*)&sq2[(8 + c) * 64 + t0];
                aq0 += q4.x * rq[c]; aq1 += q4.y * rq[c];
                aq2 += q4.z * rq[c]; aq3 += q4.w * rq[c];
                ak0 += k4.x * rk[c]; ak1 += k4.y * rk[c];
                ak2 += k4.z * rk[c]; ak3 += k4.w * rk[c];
            }
            float aqv[4] = {aq0, aq1, aq2, aq3};
            float akv[4] = {ak0, ak1, ak2, ak3};
            #pragma unroll
            for (int u = 0; u < 4; u++) {
                int t = t0 + u;
                int j = t + dmj;
                if ((unsigned)j < 64u) {
                    sqe[t * 64 + j] = aqv[u];
                    ske[t * 64 + j] = akv[u];
                }
            }
        }
    }
    __syncthreads();

    float sA = bns[g]      * rsqrtf(bns[144 + g]      + EPSV);
    float sB = bns[16 + g] * rsqrtf(bns[144 + 16 + g] + EPSV);
    float sC = bns[32 + g] * rsqrtf(bns[144 + 32 + g] + EPSV);
    float tsum = (bns[48 + g]      - bns[96 + g]      * sA)
               + (bns[48 + 16 + g] - bns[96 + 16 + g] * sB)
               + (bns[48 + 32 + g] - bns[96 + 32 + g] * sC);

    {
        int tj = tid & 15, ti = tid >> 4;
        float acc[2][4];
        #pragma unroll
        for (int u = 0; u < 2; u++)
            #pragma unroll
            for (int v = 0; v < 4; v++) acc[u][v] = 0.f;
        #pragma unroll 4
        for (int t = 0; t < 64; t++) {
            float2 qa = *(const float2*)&sqe[t * 64 + ti * 2];
            float4 kb = *(const float4*)&ske[t * 64 + tj * 4];
            float av[2] = {qa.x, qa.y};
            float bv[4] = {kb.x, kb.y, kb.z, kb.w};
            #pragma unroll
            for (int u = 0; u < 2; u++)
                #pragma unroll
                for (int v = 0; v < 4; v++) acc[u][v] += av[u] * bv[v];
        }
        #pragma unroll
        for (int u = 0; u < 2; u++) {
            int i = ti * 2 + u;
            float4 qe_i = *(const float4*)&sqe[i * 64 + tj * 4];
            float4 ke_i = *(const float4*)&ske[i * 64 + tj * 4];
            float qv[4] = {qe_i.x, qe_i.y, qe_i.z, qe_i.w};
            float kv[4] = {ke_i.x, ke_i.y, ke_i.z, ke_i.w};
            float4 o4;
            float ov[4];
            #pragma unroll
            for (int v = 0; v < 4; v++)
                ov[v] = sA * acc[u][v] + sB * qv[v] + sC * kv[v] + tsum;
            o4.x = ov[0]; o4.y = ov[1]; o4.z = ov[2]; o4.w = ov[3];
            *(float4*)&ssim[i * 68 + tj * 4] = o4;
        }
    }
    __syncthreads();

    {
        int r = tid >> 3, l = tid & 7;
        float m = -1e30f;
        #pragma unroll
        for (int jj = 0; jj < 8; jj++) m = fmaxf(m, ssim[r * 68 + l + 8 * jj]);
        m = fmaxf(m, __shfl_xor_sync(0xffffffffu, m, 1));
        m = fmaxf(m, __shfl_xor_sync(0xffffffffu, m, 2));
        m = fmaxf(m, __shfl_xor_sync(0xffffffffu, m, 4));
        float ssum = 0.f;
        #pragma unroll
        for (int jj = 0; jj < 8; jj++) {
            int id = r * 68 + l + 8 * jj;
            float e = __expf(ssim[id] - m);
            ssim[id] = e;
            ssum += e;
        }
        ssum += __shfl_xor_sync(0xffffffffu, ssum, 1);
        ssum += __shfl_xor_sync(0xffffffffu, ssum, 2);
        ssum += __shfl_xor_sync(0xffffffffu, ssum, 4);
        float inv = 1.f / ssum;
        #pragma unroll
        for (int jj = 0; jj < 8; jj++) ssim[r * 68 + l + 8 * jj] *= inv;
    }
    __syncthreads();

    {
        int i = tid & 63, cb = tid >> 6;
        int c0 = 16 + cb * 2;
        float acca0 = 0.f, acca1 = 0.f, acce0 = 0.f, acce1 = 0.f;
        #pragma unroll 4
        for (int j0 = 0; j0 < 64; j0 += 4) {
            float4 s4 = *(const float4*)&ssim[i * 68 + j0];
            float sarr[4] = {s4.x, s4.y, s4.z, s4.w};
            #pragma unroll
            for (int e = 0; e < 4; e++) {
                int j = j0 + e;
                float s = sarr[e];
                int p = i - j + 63;
                float2 v2 = *(const float2*)&svT[j * 16 + cb * 2];
                float r0 = srel[(c0 + 0) * 127 + p];
                float r1 = srel[(c0 + 1) * 127 + p];
                acca0 += s * v2.x;  acca1 += s * v2.y;
                acce0 += s * r0;    acce1 += s * r1;
            }
        }
        float accav[2] = {acca0, acca1};
        float accev[2] = {acce0, acce1};
        #pragma unroll
        for (int cc = 0; cc < 2; cc++) {
            int c = cb * 2 + cc;
            int chA = g * 32 + 2 * c, chB = chA + 1;
            float sa = bno[chA] * rsqrtf(bno[1536 + chA] + EPSV);
            float ba = bno[512 + chA] - bno[1024 + chA] * sa;
            float sb2 = bno[chB] * rsqrtf(bno[1536 + chB] + EPSV);
            float bb2 = bno[512 + chB] - bno[1024 + chB] * sb2;
            float v = accav[cc] * sa + ba + accev[cc] * sb2 + bb2;
            int ch = g * 16 + c;
            out[((size_t)(b * CO + ch)) * NP_FULL + d1 * 64 + i] = v;
        }
    }
}

// ---------------- 2x2 average pool --------------------------------------
__global__ void pool_kernel(const float* __restrict__ in, float* __restrict__ out, int C)
{
    int idx = blockIdx.x * blockDim.x + threadIdx.x;
    int total = NB * C * NP_HALF;
    if (idx >= total) return;
    int j = idx & 31;
    int i = (idx >> 5) & 31;
    int bc = idx >> 10;
    const float* p = in + (size_t)bc * NP_FULL + (size_t)(2 * i) * 64 + 2 * j;
    out[idx] = 0.25f * (p[0] + p[1] + p[64] + p[65]);
}

// ---------------- final: cbn(conv_out) + conv_res, prelu ----------------
__global__ void final_kernel(const float* __restrict__ Wo,
                             const float* __restrict__ py,
                             const float* __restrict__ Wr,
                             const float* __restrict__ px,
                             float* __restrict__ out,
                             const float* __restrict__ bn,
                             const float* __restrict__ sb,
                             const float* __restrict__ alpha_ptr)
{
    __shared__ float As[16][65];
    __shared__ float Bs[16][64];
    int tid = threadIdx.x;
    int b  = blockIdx.z;
    int o0 = blockIdx.y * 64;
    int p0 = blockIdx.x * 64;
    int ty = tid >> 4, tx = tid & 15;

    float accO[4][4], accR[4][4];
    #pragma unroll
    for (int r = 0; r < 4; r++)
        #pragma unroll
        for (int c = 0; c < 4; c++) { accO[r][c] = 0.f; accR[r][c] = 0.f; }

    const float* Xb = py + (size_t)b * CO * NP_HALF;
    for (int k0 = 0; k0 < CO; k0 += 16) {
        for (int i = tid; i < 1024; i += 256) {
            int oo = i >> 4, kk = i & 15;
            As[kk][oo] = Wo[(size_t)(o0 + oo) * CO + k0 + kk];
        }
        for (int i = tid; i < 1024; i += 256) {
            int kk = i >> 6, pp = i & 63;
            Bs[kk][pp] = Xb[(size_t)(k0 + kk) * NP_HALF + p0 + pp];
        }
        __syncthreads();
        #pragma unroll
        for (int kk = 0; kk < 16; kk++) {
            float a[4], bv[4];
            #pragma unroll
            for (int r = 0; r < 4; r++) a[r] = As[kk][ty + 16 * r];
            #pragma unroll
            for (int c = 0; c < 4; c++) bv[c] = Bs[kk][tx + 16 * c];
            #pragma unroll
            for (int r = 0; r < 4; r++)
                #pragma unroll
                for (int c = 0; c < 4; c++) accO[r][c] += a[r] * bv[c];
        }
        __syncthreads();
    }

    const float* Xr = px + (size_t)b * CINC * NP_HALF;
    for (int k0 = 0; k0 < CINC; k0 += 16) {
        for (int i = tid; i < 1024; i += 256) {
            int oo = i >> 4, kk = i & 15;
            As[kk][oo] = Wr[(size_t)(o0 + oo) * CINC + k0 + kk];
        }
        for (int i = tid; i < 1024; i += 256) {
            int kk = i >> 6, pp = i & 63;
            Bs[kk][pp] = Xr[(size_t)(k0 + kk) * NP_HALF + p0 + pp];
        }
        __syncthreads();
        #pragma unroll
        for (int kk = 0; kk < 16; kk++) {
            float a[4], bv[4];
            #pragma unroll
            for (int r = 0; r < 4; r++) a[r] = As[kk][ty + 16 * r];
            #pragma unroll
            for (int c = 0; c < 4; c++) bv[c] = Bs[kk][tx + 16 * c];
            #pragma unroll
            for (int r = 0; r < 4; r++)
                #pragma unroll
                for (int c = 0; c < 4; c++) accR[r][c] += a[r] * bv[c];
        }
        __syncthreads();
    }

    float alpha = *alpha_ptr;
    #pragma unroll
    for (int r = 0; r < 4; r++) {
        int o = o0 + ty + 16 * r;
        float bsc = bn[o] * rsqrtf(bn[3 * CO + o] + EPSV);
        float bbi = bn[CO + o] - bn[2 * CO + o] * bsc;
        float slat = sb[b * 512 + o];
        float blat = sb[b * 512 + 256 + o];
        #pragma unroll
        for (int c = 0; c < 4; c++) {
            int p = p0 + tx + 16 * c;
            float v = (accO[r][c] * bsc + bbi) * slat + blat + accR[r][c];
            v = v > 0.f ? v : alpha * v;
            out[((size_t)(b * CO + o)) * NP_HALF + p] = v;
        }
    }
}

// ---------------- launcher ----------------------------------------------
extern "C" void kernel_launch(void* const* d_in, const int* in_sizes, int n_in,
                              void* d_out, int out_size)
{
    const float* x         = (const float*)d_in[0];
    const float* latent    = (const float*)d_in[1];
    const float* w_in      = (const float*)d_in[2];
    const float* bn_in     = (const float*)d_in[3];
    const float* lin_in    = (const float*)d_in[4];
    const float* alpha_in  = (const float*)d_in[5];
    const float* a0_wqkv   = (const float*)d_in[6];
    const float* a0_bn_qkv = (const float*)d_in[7];
    const float* a0_bn_sim = (const float*)d_in[8];
    const float* a0_bn_out = (const float*)d_in[9];
    const float* a0_rel    = (const float*)d_in[10];
    const float* a1_wqkv   = (const float*)d_in[11];
    const float* a1_bn_qkv = (const float*)d_in[12];
    const float* a1_bn_sim = (const float*)d_in[13];
    const float* a1_bn_out = (const float*)d_in[14];
    const float* a1_rel    = (const float*)d_in[15];
    const float* w_out     = (const float*)d_in[16];
    const float* bn_out    = (const float*)d_in[17];
    const float* lin_out   = (const float*)d_in[18];
    const float* w_res     = (const float*)d_in[19];
    const float* alpha_fin = (const float*)d_in[20];
    float* out = (float*)d_out;

    float *yb, *ytb, *qkvb, *pyb, *pxb, *sbb;
    cudaGetSymbolAddress((void**)&yb,   g_y);
    cudaGetSymbolAddress((void**)&ytb,  g_yt);
    cudaGetSymbolAddress((void**)&qkvb, g_qkv);
    cudaGetSymbolAddress((void**)&pyb,  g_py);
    cudaGetSymbolAddress((void**)&pxb,  g_px);
    cudaGetSymbolAddress((void**)&sbb,  g_sb);

    cudaFuncSetAttribute(attn_kernel, cudaFuncAttributeMaxDynamicSharedMemorySize,
                         ATTN_SMEM_BYTES);

    dim3 tgrid(2, 2, NB * CO);
    dim3 tblk(32, 8);

    // 1. latent-conditioned scale/bias
    sb_kernel<<<16, 256>>>(latent, lin_in, lin_out, sbb);

    // 2. y = prelu(cbn(conv1x1(w_in, x)))   layout [h][w]
    {
        dim3 g(NP_FULL / 128, CO / 128, NB);
        conv1x1_tc_kernel<<<g, 256>>>(w_in, x, yb, CINC, CO, NP_FULL,
                                      bn_in, sbb, alpha_in, 0);
    }

    // 3. transpose y -> yt ([w][h]); qkv conv a0 on yt; attn0 (over h)
    transpose_kernel<<<tgrid, tblk>>>(yb, ytb);
    {
        dim3 g(NP_FULL / 128, (2 * CO) / 128, NB);
        conv1x1_tc_kernel<<<g, 256>>>(a0_wqkv, ytb, qkvb, CO, 2 * CO, NP_FULL,
                                      a0_bn_qkv, nullptr, nullptr, 1);
        dim3 ga(256, NG);
        attn_kernel<<<ga, 512, ATTN_SMEM_BYTES>>>(qkvb, yb, a0_rel,
                                                  a0_bn_sim, a0_bn_out);
        // y now holds [w][h] order
    }

    // 4. transpose y -> yt ([h][w]); qkv conv a1 on yt; attn1 (over w)
    transpose_kernel<<<tgrid, tblk>>>(yb, ytb);
    {
        dim3 g(NP_FULL / 128, (2 * CO) / 128, NB);
        conv1x1_tc_kernel<<<g, 256>>>(a1_wqkv, ytb, qkvb, CO, 2 * CO, NP_FULL,
                                      a1_bn_qkv, nullptr, nullptr, 1);
        dim3 ga(256, NG);
        attn_kernel<<<ga, 512, ATTN_SMEM_BYTES>>>(qkvb, yb, a1_rel,
                                                  a1_bn_sim, a1_bn_out);
        // y now holds normal [h][w] order
    }

    // 5. pools
    pool_kernel<<<(NB * CO * NP_HALF + 255) / 256, 256>>>(yb, pyb, CO);
    pool_kernel<<<(NB * CINC * NP_HALF + 255) / 256, 256>>>(x, pxb, CINC);

    // 6. final
    {
        dim3 g(NP_HALF / 64, CO / 64, NB);
        final_kernel<<<g, 256>>>(w_out, pyb, w_res, pxb, out,
                                 bn_out, sbb + 2048, alpha_fin);
    }
}